// round 12
// baseline (speedup 1.0000x reference)
#include <cuda_runtime.h>
#include <math.h>

typedef unsigned long long ull;

// ---------------- problem constants ----------------
#define Bn    4
#define CIN   21
#define HL    81
#define WL    81
#define HW    6561
#define HWO   104976
#define WOUTX 324
#define XPW   88
#define XPP   7304        // 83*88

#define OUT_V_OFF 8817984
#define OUT_G_OFF 9027936

// ---------------- scratch (zero-init BSS: halos stay zero forever) --------
__device__ float g_xpad[Bn * CIN * XPP];
__device__ float g_hidden[Bn * 96 * XPP];

// ---------------- packed fp32x2 helpers ----------------
__device__ __forceinline__ ull pkf2(float lo, float hi) {
    ull r; asm("mov.b64 %0, {%1,%2};" : "=l"(r) : "f"(lo), "f"(hi)); return r;
}
__device__ __forceinline__ void upkf2(ull v, float& lo, float& hi) {
    asm("mov.b64 {%0,%1}, %2;" : "=f"(lo), "=f"(hi) : "l"(v));
}
__device__ __forceinline__ void ffma2(ull& d, ull a, ull b) {
    asm("fma.rn.f32x2 %0, %1, %2, %0;" : "+l"(d) : "l"(a), "l"(b));
}
__device__ __forceinline__ ull hilo(ull a, ull b) {
    float al, ah, bl, bh; upkf2(a, al, ah); upkf2(b, bl, bh); return pkf2(ah, bl);
}

__device__ __forceinline__ float fast_tanh(float x) {
    const float e2 = __expf(2.0f * x);
    return 1.0f - __fdividef(2.0f, e2 + 1.0f);
}
__device__ __forceinline__ float fast_sigmoid(float x) {
    return __fdividef(1.0f, 1.0f + __expf(-x));
}

// ==========================================================================
// Kernel 0: interior-only copy x -> xpad, 4 batches per thread (MLP 4).
// grid (27, 21); block (81, 3).
// ==========================================================================
__global__ __launch_bounds__(243) void pad_kernel(const float* __restrict__ x)
{
    const int c   = blockIdx.y;                         // channel 0..20
    const int row = blockIdx.x * 3 + threadIdx.y;       // 0..80
    const int col = threadIdx.x;                        // 0..80
    const int srel = row * WL + col;
    const int drel = (row + 1) * XPW + col + 1;
#pragma unroll
    for (int b = 0; b < Bn; ++b)
        g_xpad[(b * CIN + c) * XPP + drel] = x[(b * CIN + c) * HW + srel];
}

// ==========================================================================
// Kernel 1: conv1 (21 -> 96), ReLU. R11 double-buffered version (exact).
// ==========================================================================
#define C1_F4 (3 * 29 * 22)
__global__ __launch_bounds__(192) void conv1_kernel(
    const float* __restrict__ w1o, const float* __restrict__ b1o,
    const float* __restrict__ w1g, const float* __restrict__ b1g)
{
    __shared__ __align__(16) float sx[2][3 * 29 * XPW];
    __shared__ ull sw2[4 * 189];

    const int tile = blockIdx.x;
    const int cg   = blockIdx.y;
    const int b    = blockIdx.z;
    const int r0   = tile * 27;
    const int tid  = threadIdx.x;

    for (int i = tid; i < 4 * 189; i += 192) {
        const int co = i / 189, j = i - co * 189;
        const int co_out = cg * 4 + co;
        const float w = (co_out < 48) ? w1o[co_out * 189 + j] : w1g[(co_out - 48) * 189 + j];
        sw2[i] = pkf2(w, w);
    }

    const bool active = tid < 189;
    const int trp = active ? (tid / 21) : 0;
    const int tc  = active ? ((tid - trp * 21) * 4) : 0;
    const int trp3 = trp * 3;
    const int nvalid = (tc == 80) ? 1 : 4;

    {
        const float4* src = (const float4*)g_xpad;
        for (int i = tid; i < C1_F4; i += 192) {
            const int c  = i / 638;
            const int rm = i - c * 638;
            const int lr = rm / 22;
            const int f4 = rm - lr * 22;
            ((float4*)sx[0])[(c * 29 + lr) * 22 + f4] =
                src[((b * CIN + c) * XPP + (r0 + lr) * XPW) / 4 + f4];
        }
    }
    __syncthreads();

    ull acc[4][3][2];
#pragma unroll
    for (int co = 0; co < 4; ++co)
#pragma unroll
        for (int r = 0; r < 3; ++r) { acc[co][r][0] = 0ULL; acc[co][r][1] = 0ULL; }

    for (int cc = 0; cc < 7; ++cc) {
        const int cur = cc & 1;
        if (cc < 6) {
            const float4* src = (const float4*)g_xpad;
#pragma unroll 2
            for (int i = tid; i < C1_F4; i += 192) {
                const int c  = i / 638;
                const int rm = i - c * 638;
                const int lr = rm / 22;
                const int f4 = rm - lr * 22;
                ((float4*)sx[cur ^ 1])[(c * 29 + lr) * 22 + f4] =
                    src[((b * CIN + (cc + 1) * 3 + c) * XPP + (r0 + lr) * XPW) / 4 + f4];
            }
        }

        if (active) {
#pragma unroll
            for (int c = 0; c < 3; ++c) {
                ull PA[5], PAB[5], PB[5], PBC[5], PC[5];
#pragma unroll
                for (int rr = 0; rr < 5; ++rr) {
                    const float* rp = &sx[cur][(c * 29 + trp3 + rr) * XPW + tc];
                    const ull A  = *(const ull*)rp;
                    const ull Bv = *(const ull*)(rp + 2);
                    const ull Cv = *(const ull*)(rp + 4);
                    PA[rr] = A; PB[rr] = Bv; PC[rr] = Cv;
                    PAB[rr] = hilo(A, Bv); PBC[rr] = hilo(Bv, Cv);
                }
                const int wb = (cc * 3 + c) * 9;
#pragma unroll
                for (int ky = 0; ky < 3; ++ky)
#pragma unroll
                    for (int kx = 0; kx < 3; ++kx)
#pragma unroll
                        for (int co = 0; co < 4; ++co) {
                            const ull w = sw2[co * 189 + wb + ky * 3 + kx];
#pragma unroll
                            for (int r = 0; r < 3; ++r) {
                                const int rw = r + ky;
                                ffma2(acc[co][r][0],
                                      kx == 0 ? PA[rw] : (kx == 1 ? PAB[rw] : PB[rw]), w);
                                ffma2(acc[co][r][1],
                                      kx == 0 ? PB[rw] : (kx == 1 ? PBC[rw] : PC[rw]), w);
                            }
                        }
            }
        }
        __syncthreads();
    }

    if (active) {
#pragma unroll
        for (int co = 0; co < 4; ++co) {
            const int co_out = cg * 4 + co;
            const float bias = (co_out < 48) ? b1o[co_out] : b1g[co_out - 48];
#pragma unroll
            for (int r = 0; r < 3; ++r) {
                const int orow = r0 + trp3 + r;
                float* dst = &g_hidden[(b * 96 + co_out) * XPP + (orow + 1) * XPW + tc + 1];
                float v[4];
                upkf2(acc[co][r][0], v[0], v[1]);
                upkf2(acc[co][r][1], v[2], v[3]);
#pragma unroll
                for (int p = 0; p < 4; ++p)
                    if (p < nvalid) dst[p] = fmaxf(v[p] + bias, 0.f);
            }
        }
    }
}

// ==========================================================================
// Kernel 2 (FUSED): conv2 heads + mask + upsample, 1-ROW tiles.
// grid (81 rows, Bn); block 192 (189 active in phase 1).
// Phase 1: thread = 1 row x 4 px x 1 co; 16 double-buffered chunks of 6 ch.
// Phase 2: 81 threads mask+g_up; 81 threads wx table; 4 threads wy table.
// Phase 3: 1701 tasks (21 ch x 81 px).
// ==========================================================================
#define C2F_F4 396   // float4 per chunk (6 ch x 3 rows x 22)
__global__ __launch_bounds__(192) void conv2fused_kernel(
    const float* __restrict__ w2o, const float* __restrict__ b2o,
    const float* __restrict__ w2g, const float* __restrict__ b2g,
    const float* __restrict__ beta, const float* __restrict__ x,
    float* __restrict__ out)
{
    __shared__ __align__(16) unsigned char smem[43776];
    float* sx0   = (float*)smem;                        // 6336 B
    float* sx1   = (float*)(smem + 6336);               // 6336 B
    float* sraw  = (float*)smem;                        // [9][84] overlay sx0
    ull*   sw2   = (ull*)(smem + 12672);                // 3888 ull = 31104 B
    float* smask = (float*)(smem + 12672);              // 81*12 f   (overlay sw2)
    ull*   swx   = (ull*)(smem + 12672 + 3888);         // 81*6 ull
    ull*   swy   = (ull*)(smem + 12672 + 3888 + 3888);  // 12 ull

    const int y   = blockIdx.x;          // output row 0..80
    const int b   = blockIdx.y;
    const int tid = threadIdx.x;
    const float sc = 80.0f / 323.0f;

    for (int i = tid; i < 9 * 432; i += 192) {
        const int co = i / 432, j = i - co * 432;
        const float w = (co < 8) ? w2o[co * 432 + j] : w2g[j];
        sw2[i] = pkf2(w, w);
    }

    const bool active = tid < 189;
    const int co  = active ? (tid / 21) : 0;        // 0..8
    const int s   = active ? (tid - co * 21) : 0;
    const int tc  = s * 4;
    const int nvalid = (tc == 80) ? 1 : 4;
    const int csel = (co == 8) ? 3 : 0;

    // stage chunk 0 (padded rows y..y+2)
    {
        const float4* src = (const float4*)g_hidden;
        for (int i = tid; i < C2F_F4; i += 192) {
            const int c  = i / 66;
            const int rm = i - c * 66;
            const int lr = rm / 22;
            const int f4 = rm - lr * 22;
            const int ch = (c < 3) ? c : (48 + c - 3);
            ((float4*)sx0)[(c * 3 + lr) * 22 + f4] =
                src[((b * 96 + ch) * XPP + (y + lr) * XPW) / 4 + f4];
        }
    }
    __syncthreads();

    ull a0 = 0ULL, a1 = 0ULL;

    for (int cc = 0; cc < 16; ++cc) {
        float* cursx = (cc & 1) ? sx1 : sx0;
        float* nxtsx = (cc & 1) ? sx0 : sx1;

        if (cc < 15) {
            const float4* src = (const float4*)g_hidden;
            for (int i = tid; i < C2F_F4; i += 192) {
                const int c  = i / 66;
                const int rm = i - c * 66;
                const int lr = rm / 22;
                const int f4 = rm - lr * 22;
                const int ch = (c < 3) ? ((cc + 1) * 3 + c) : (48 + (cc + 1) * 3 + (c - 3));
                ((float4*)nxtsx)[(c * 3 + lr) * 22 + f4] =
                    src[((b * 96 + ch) * XPP + (y + lr) * XPW) / 4 + f4];
            }
        }

        if (active) {
#pragma unroll
            for (int c = 0; c < 3; ++c) {
                ull PA[3], PAB[3], PB[3], PBC[3], PC[3];
#pragma unroll
                for (int rr = 0; rr < 3; ++rr) {
                    const float* rp = &cursx[((csel + c) * 3 + rr) * XPW + tc];
                    const ull A  = *(const ull*)rp;
                    const ull Bv = *(const ull*)(rp + 2);
                    const ull Cv = *(const ull*)(rp + 4);
                    PA[rr] = A; PB[rr] = Bv; PC[rr] = Cv;
                    PAB[rr] = hilo(A, Bv); PBC[rr] = hilo(Bv, Cv);
                }
                const int wb = co * 432 + (cc * 3 + c) * 9;
#pragma unroll
                for (int ky = 0; ky < 3; ++ky)
#pragma unroll
                    for (int kx = 0; kx < 3; ++kx) {
                        const ull w = sw2[wb + ky * 3 + kx];
                        ffma2(a0, kx == 0 ? PA[ky] : (kx == 1 ? PAB[ky] : PB[ky]), w);
                        ffma2(a1, kx == 0 ? PB[ky] : (kx == 1 ? PBC[ky] : PC[ky]), w);
                    }
            }
        }
        __syncthreads();
    }

    // ---- epilogue: activations -> sraw (+ v -> out) ----
    if (active) {
        const float bias = (co < 8) ? b2o[co] : b2g[0];
        float v[4];
        upkf2(a0, v[0], v[1]);
        upkf2(a1, v[2], v[3]);
#pragma unroll
        for (int p = 0; p < 4; ++p) {
            if (p >= nvalid) continue;
            const float raw = v[p] + bias;
            if (co < 8) {
                const float t = fast_tanh(raw);
                sraw[co * 84 + tc + p] = t;
                out[OUT_V_OFF + (b * 8 + co) * HW + y * WL + tc + p] = t;
            } else {
                sraw[8 * 84 + tc + p] = fast_sigmoid(raw);
            }
        }
    }
    __syncthreads();

    // ---- phase 2: masks + geometry + g_up ----
    if (tid < 81) {
        const int xx = tid;

        const float p0 = sraw[0 * 84 + xx] - sraw[4 * 84 + xx];
        const float p1 = sraw[1 * 84 + xx] - sraw[5 * 84 + xx];
        const float p2 = sraw[2 * 84 + xx] - sraw[6 * 84 + xx];
        const float p3 = sraw[3 * 84 + xx] - sraw[7 * 84 + xx];
        const float g  = sraw[8 * 84 + xx];

        const float k00 = (p0 + p1 + p2) * 0.125f;
        const float k01 = (p1 + p2 + p3) * 0.125f;
        const float k02 = (-p0 + p2 + p3) * 0.125f;
        const float k10 = (p0 + p1 - p3) * 0.125f;

        float kb[9];
        kb[0] = k00;  kb[1] = k01;  kb[2] = k02;
        kb[3] = k10;  kb[4] = 2.5f; kb[5] = -k10;
        kb[6] = -k02; kb[7] = -k01; kb[8] = -k00;

        float mx = kb[0];
#pragma unroll
        for (int n = 1; n < 9; ++n) mx = fmaxf(mx, kb[n]);
        float e[9], se = 0.f;
#pragma unroll
        for (int n = 0; n < 9; ++n) { e[n] = __expf((kb[n] - mx) * 2.0f); se += e[n]; }
        const float inv_se = __fdividef(1.0f, se);

        const float mean = 2.5f / 9.0f;
        float sa = 0.f;
#pragma unroll
        for (int n = 0; n < 9; ++n) sa += fabsf(kb[n] - mean);
        const float hinv = __fdividef(1.0f, sa + 1e-8f);

        const float lam = 0.15f * (1.0f - g);
        const float tbg = tanhf(beta[0]) * g;

        float w[12];
#pragma unroll
        for (int n = 0; n < 9; ++n) w[n] = lam * e[n] * inv_se + tbg * (kb[n] - mean) * hinv;
        w[9]  = 1.0f - lam;
        w[10] = g;
        w[11] = 0.f;

        float* dm = &smask[xx * 12];
        ((float4*)dm)[0] = make_float4(w[0], w[1], w[2], w[3]);
        ((float4*)dm)[1] = make_float4(w[4], w[5], w[6], w[7]);
        ((float4*)dm)[2] = make_float4(w[8], w[9], w[10], w[11]);

        const float4 gq = make_float4(g, g, g, g);
        float* gd = &out[OUT_G_OFF + b * HWO + (y * 4) * WOUTX + xx * 4];
#pragma unroll
        for (int jy = 0; jy < 4; ++jy) *(float4*)(gd + jy * WOUTX) = gq;
    } else if (tid >= 96 && tid < 177) {
        const int q = tid - 96;           // xx coordinate
        float w3[4][3];
#pragma unroll
        for (int j = 0; j < 4; ++j) {
            const float f = (float)(q * 4 + j) * sc;
            int i0 = (int)f; if (i0 > 79) i0 = 79;
            const float w = f - (float)i0;
            const bool lo = (i0 != q);
            w3[j][0] = lo ? (1.f - w) : 0.f;
            w3[j][1] = lo ? w : (1.f - w);
            w3[j][2] = lo ? 0.f : w;
        }
#pragma unroll
        for (int p = 0; p < 2; ++p)
#pragma unroll
            for (int j = 0; j < 3; ++j)
                swx[q * 6 + p * 3 + j] = pkf2(w3[2 * p][j], w3[2 * p + 1][j]);
    } else if (tid >= 177 && tid < 181) {
        const int jy = tid - 177;
        const float f = (float)(y * 4 + jy) * sc;
        int i0 = (int)f; if (i0 > 79) i0 = 79;
        const float w = f - (float)i0;
        const bool lo = (i0 != y);
        const float t0 = lo ? (1.f - w) : 0.f;
        const float t1 = lo ? w : (1.f - w);
        const float t2 = lo ? 0.f : w;
        swy[jy * 3 + 0] = pkf2(t0, t0);
        swy[jy * 3 + 1] = pkf2(t1, t1);
        swy[jy * 3 + 2] = pkf2(t2, t2);
    }
    __syncthreads();

    // ---- phase 3: upsample. 1701 tasks = 21 ch x 81 px ----
    const int ym = (y == 0) ? 1 : y - 1,   ypl = (y == HL - 1) ? HL - 2 : y + 1;
    const int ry[3] = {ym, y, ypl};

    for (int t = tid; t < 1701; t += 192) {
        const int ch = t / 81;
        const int xx = t - ch * 81;

        const float* wsrc = &smask[xx * 12];
        const float4 m0 = ((const float4*)wsrc)[0];
        const float4 m1 = ((const float4*)wsrc)[1];
        const float4 m2 = ((const float4*)wsrc)[2];
        const float wm[9] = {m0.x, m0.y, m0.z, m0.w, m1.x, m1.y, m1.z, m1.w, m2.x};
        const float oml = m2.y;
        const ull oml2 = pkf2(oml, oml);

        const int xm = (xx == 0) ? 1 : xx - 1, xpl = (xx == WL - 1) ? WL - 2 : xx + 1;
        const int rx[3] = {xm, xx, xpl};

        const float* xb = x + (b * CIN + ch) * HW;
        float tv[3][3];
#pragma unroll
        for (int i = 0; i < 3; ++i)
#pragma unroll
            for (int j = 0; j < 3; ++j)
                tv[i][j] = xb[ry[i] * WL + rx[j]];

        float yc = 0.f;
#pragma unroll
        for (int i = 0; i < 3; ++i)
#pragma unroll
            for (int j = 0; j < 3; ++j)
                yc += tv[i][j] * wm[i * 3 + j];
        const ull yc2 = pkf2(yc, yc);

        ull wxp[6];
#pragma unroll
        for (int i = 0; i < 6; ++i) wxp[i] = swx[xx * 6 + i];

        ull cvp[3][2];
#pragma unroll
        for (int i = 0; i < 3; ++i) { cvp[i][0] = 0ULL; cvp[i][1] = 0ULL; }
#pragma unroll
        for (int i = 0; i < 3; ++i)
#pragma unroll
            for (int j = 0; j < 3; ++j) {
                const ull td = pkf2(tv[i][j], tv[i][j]);
                ffma2(cvp[i][0], td, wxp[j]);
                ffma2(cvp[i][1], td, wxp[3 + j]);
            }

        float* dst = &out[(b * CIN + ch) * HWO + (y * 4) * WOUTX + xx * 4];
#pragma unroll
        for (int jy = 0; jy < 4; ++jy) {
            ull bil0 = 0ULL, bil1 = 0ULL;
#pragma unroll
            for (int i = 0; i < 3; ++i) {
                const ull wy = swy[jy * 3 + i];
                ffma2(bil0, cvp[i][0], wy);
                ffma2(bil1, cvp[i][1], wy);
            }
            ull rr0 = yc2, rr1 = yc2;
            ffma2(rr0, bil0, oml2);
            ffma2(rr1, bil1, oml2);
            float o0, o1, o2, o3;
            upkf2(rr0, o0, o1);
            upkf2(rr1, o2, o3);
            *(float4*)(dst + jy * WOUTX) = make_float4(o0, o1, o2, o3);
        }
    }
}

// ==========================================================================
extern "C" void kernel_launch(void* const* d_in, const int* in_sizes, int n_in,
                              void* d_out, int out_size)
{
    const float* x    = (const float*)d_in[0];
    const float* w1o  = (const float*)d_in[1];
    const float* b1o  = (const float*)d_in[2];
    const float* w2o  = (const float*)d_in[3];
    const float* b2o  = (const float*)d_in[4];
    const float* w1g  = (const float*)d_in[5];
    const float* b1g  = (const float*)d_in[6];
    const float* w2g  = (const float*)d_in[7];
    const float* b2g  = (const float*)d_in[8];
    const float* beta = (const float*)d_in[9];
    float* out = (float*)d_out;

    pad_kernel<<<dim3(27, CIN), dim3(81, 3)>>>(x);
    conv1_kernel<<<dim3(3, 24, Bn), 192>>>(w1o, b1o, w1g, b1g);
    conv2fused_kernel<<<dim3(81, Bn), 192>>>(w2o, b2o, w2g, b2g, beta, x, out);
}

// round 13
// speedup vs baseline: 1.0722x; 1.0722x over previous
#include <cuda_runtime.h>
#include <math.h>

typedef unsigned long long ull;

// ---------------- problem constants ----------------
#define Bn    4
#define CIN   21
#define HL    81
#define WL    81
#define HW    6561
#define HWO   104976
#define WOUTX 324
#define XPW   88
#define XPP   7304        // 83*88

#define OUT_V_OFF 8817984
#define OUT_G_OFF 9027936

// ---------------- scratch (zero-init BSS: halos stay zero forever) --------
__device__ float g_xpad[Bn * CIN * XPP];
__device__ float g_hidden[Bn * 96 * XPP];

// ---------------- packed fp32x2 helpers ----------------
__device__ __forceinline__ ull pkf2(float lo, float hi) {
    ull r; asm("mov.b64 %0, {%1,%2};" : "=l"(r) : "f"(lo), "f"(hi)); return r;
}
__device__ __forceinline__ void upkf2(ull v, float& lo, float& hi) {
    asm("mov.b64 {%0,%1}, %2;" : "=f"(lo), "=f"(hi) : "l"(v));
}
__device__ __forceinline__ void ffma2(ull& d, ull a, ull b) {
    asm("fma.rn.f32x2 %0, %1, %2, %0;" : "+l"(d) : "l"(a), "l"(b));
}
__device__ __forceinline__ ull hilo(ull a, ull b) {
    float al, ah, bl, bh; upkf2(a, al, ah); upkf2(b, bl, bh); return pkf2(ah, bl);
}

__device__ __forceinline__ float fast_tanh(float x) {
    const float e2 = __expf(2.0f * x);
    return 1.0f - __fdividef(2.0f, e2 + 1.0f);
}
__device__ __forceinline__ float fast_sigmoid(float x) {
    return __fdividef(1.0f, 1.0f + __expf(-x));
}

// ==========================================================================
// Kernel 0: interior-only copy x -> xpad, 4 batches per thread (MLP 4).
// grid (27, 21); block (81, 3).   [R12 version, measured -0.8us]
// ==========================================================================
__global__ __launch_bounds__(243) void pad_kernel(const float* __restrict__ x)
{
    const int c   = blockIdx.y;
    const int row = blockIdx.x * 3 + threadIdx.y;
    const int col = threadIdx.x;
    const int srel = row * WL + col;
    const int drel = (row + 1) * XPW + col + 1;
#pragma unroll
    for (int b = 0; b < Bn; ++b)
        g_xpad[(b * CIN + c) * XPP + drel] = x[(b * CIN + c) * HW + srel];
}

// ==========================================================================
// Kernel 1: conv1 (21 -> 96), ReLU. R11 double-buffered version.
// grid (3, 24, Bn); block 192 (189 active). 3 rows x 4 px x 4 co / thread.
// ==========================================================================
#define C1_F4 (3 * 29 * 22)
__global__ __launch_bounds__(192) void conv1_kernel(
    const float* __restrict__ w1o, const float* __restrict__ b1o,
    const float* __restrict__ w1g, const float* __restrict__ b1g)
{
    __shared__ __align__(16) float sx[2][3 * 29 * XPW];
    __shared__ ull sw2[4 * 189];

    const int tile = blockIdx.x;
    const int cg   = blockIdx.y;
    const int b    = blockIdx.z;
    const int r0   = tile * 27;
    const int tid  = threadIdx.x;

    for (int i = tid; i < 4 * 189; i += 192) {
        const int co = i / 189, j = i - co * 189;
        const int co_out = cg * 4 + co;
        const float w = (co_out < 48) ? w1o[co_out * 189 + j] : w1g[(co_out - 48) * 189 + j];
        sw2[i] = pkf2(w, w);
    }

    const bool active = tid < 189;
    const int trp = active ? (tid / 21) : 0;
    const int tc  = active ? ((tid - trp * 21) * 4) : 0;
    const int trp3 = trp * 3;
    const int nvalid = (tc == 80) ? 1 : 4;

    {
        const float4* src = (const float4*)g_xpad;
        for (int i = tid; i < C1_F4; i += 192) {
            const int c  = i / 638;
            const int rm = i - c * 638;
            const int lr = rm / 22;
            const int f4 = rm - lr * 22;
            ((float4*)sx[0])[(c * 29 + lr) * 22 + f4] =
                src[((b * CIN + c) * XPP + (r0 + lr) * XPW) / 4 + f4];
        }
    }
    __syncthreads();

    ull acc[4][3][2];
#pragma unroll
    for (int co = 0; co < 4; ++co)
#pragma unroll
        for (int r = 0; r < 3; ++r) { acc[co][r][0] = 0ULL; acc[co][r][1] = 0ULL; }

    for (int cc = 0; cc < 7; ++cc) {
        const int cur = cc & 1;
        if (cc < 6) {
            const float4* src = (const float4*)g_xpad;
#pragma unroll 2
            for (int i = tid; i < C1_F4; i += 192) {
                const int c  = i / 638;
                const int rm = i - c * 638;
                const int lr = rm / 22;
                const int f4 = rm - lr * 22;
                ((float4*)sx[cur ^ 1])[(c * 29 + lr) * 22 + f4] =
                    src[((b * CIN + (cc + 1) * 3 + c) * XPP + (r0 + lr) * XPW) / 4 + f4];
            }
        }

        if (active) {
#pragma unroll
            for (int c = 0; c < 3; ++c) {
                ull PA[5], PAB[5], PB[5], PBC[5], PC[5];
#pragma unroll
                for (int rr = 0; rr < 5; ++rr) {
                    const float* rp = &sx[cur][(c * 29 + trp3 + rr) * XPW + tc];
                    const ull A  = *(const ull*)rp;
                    const ull Bv = *(const ull*)(rp + 2);
                    const ull Cv = *(const ull*)(rp + 4);
                    PA[rr] = A; PB[rr] = Bv; PC[rr] = Cv;
                    PAB[rr] = hilo(A, Bv); PBC[rr] = hilo(Bv, Cv);
                }
                const int wb = (cc * 3 + c) * 9;
#pragma unroll
                for (int ky = 0; ky < 3; ++ky)
#pragma unroll
                    for (int kx = 0; kx < 3; ++kx)
#pragma unroll
                        for (int co = 0; co < 4; ++co) {
                            const ull w = sw2[co * 189 + wb + ky * 3 + kx];
#pragma unroll
                            for (int r = 0; r < 3; ++r) {
                                const int rw = r + ky;
                                ffma2(acc[co][r][0],
                                      kx == 0 ? PA[rw] : (kx == 1 ? PAB[rw] : PB[rw]), w);
                                ffma2(acc[co][r][1],
                                      kx == 0 ? PB[rw] : (kx == 1 ? PBC[rw] : PC[rw]), w);
                            }
                        }
            }
        }
        if (cc < 6) __syncthreads();   // uniform condition; no hazard after last chunk
    }

    if (active) {
#pragma unroll
        for (int co = 0; co < 4; ++co) {
            const int co_out = cg * 4 + co;
            const float bias = (co_out < 48) ? b1o[co_out] : b1g[co_out - 48];
#pragma unroll
            for (int r = 0; r < 3; ++r) {
                const int orow = r0 + trp3 + r;
                float* dst = &g_hidden[(b * 96 + co_out) * XPP + (orow + 1) * XPW + tc + 1];
                float v[4];
                upkf2(acc[co][r][0], v[0], v[1]);
                upkf2(acc[co][r][1], v[2], v[3]);
#pragma unroll
                for (int p = 0; p < 4; ++p)
                    if (p < nvalid) dst[p] = fmaxf(v[p] + bias, 0.f);
            }
        }
    }
}

// ==========================================================================
// Kernel 2 (FUSED): conv2 heads + mask + upsample. R11 version (3-row tiles,
// 576 threads, double-buffered phase 1).
// ==========================================================================
#define C2F_F4 660
__global__ __launch_bounds__(576) void conv2fused_kernel(
    const float* __restrict__ w2o, const float* __restrict__ b2o,
    const float* __restrict__ w2g, const float* __restrict__ b2g,
    const float* __restrict__ beta, const float* __restrict__ x,
    float* __restrict__ out)
{
    __shared__ __align__(16) unsigned char smem[52224];
    float* sx0   = (float*)smem;
    float* sx1   = (float*)(smem + 10560);
    float* sraw  = (float*)smem;                        // overlay sx0
    ull*   sw2   = (ull*)(smem + 21120);
    float* smask = (float*)(smem + 21120);              // overlay sw2
    ull*   swx   = (ull*)(smem + 21120 + 11664);
    ull*   swy   = (ull*)(smem + 21120 + 11664 + 3888);

    const int tile = blockIdx.x;
    const int b    = blockIdx.y;
    const int r0   = tile * 3;
    const int tid  = threadIdx.x;
    const float sc = 80.0f / 323.0f;

    for (int i = tid; i < 9 * 432; i += 576) {
        const int co = i / 432, j = i - co * 432;
        const float w = (co < 8) ? w2o[co * 432 + j] : w2g[j];
        sw2[i] = pkf2(w, w);
    }

    const bool active = tid < 567;
    const int co  = active ? (tid / 63) : 0;
    const int s   = active ? (tid - co * 63) : 0;
    const int row = s / 21;
    const int tc  = (s - row * 21) * 4;
    const int nvalid = (tc == 80) ? 1 : 4;
    const int csel = (co == 8) ? 3 : 0;

    {
        const float4* src = (const float4*)g_hidden;
        for (int i = tid; i < C2F_F4; i += 576) {
            const int c  = i / 110;
            const int rm = i - c * 110;
            const int lr = rm / 22;
            const int f4 = rm - lr * 22;
            const int ch = (c < 3) ? c : (48 + c - 3);
            ((float4*)sx0)[(c * 5 + lr) * 22 + f4] =
                src[((b * 96 + ch) * XPP + (r0 + lr) * XPW) / 4 + f4];
        }
    }
    __syncthreads();

    ull a0 = 0ULL, a1 = 0ULL;

    for (int cc = 0; cc < 16; ++cc) {
        float* cursx = (cc & 1) ? sx1 : sx0;
        float* nxtsx = (cc & 1) ? sx0 : sx1;

        if (cc < 15) {
            const float4* src = (const float4*)g_hidden;
            for (int i = tid; i < C2F_F4; i += 576) {
                const int c  = i / 110;
                const int rm = i - c * 110;
                const int lr = rm / 22;
                const int f4 = rm - lr * 22;
                const int ch = (c < 3) ? ((cc + 1) * 3 + c) : (48 + (cc + 1) * 3 + (c - 3));
                ((float4*)nxtsx)[(c * 5 + lr) * 22 + f4] =
                    src[((b * 96 + ch) * XPP + (r0 + lr) * XPW) / 4 + f4];
            }
        }

        if (active) {
#pragma unroll
            for (int c = 0; c < 3; ++c) {
                ull PA[3], PAB[3], PB[3], PBC[3], PC[3];
#pragma unroll
                for (int rr = 0; rr < 3; ++rr) {
                    const float* rp = &cursx[((csel + c) * 5 + row + rr) * XPW + tc];
                    const ull A  = *(const ull*)rp;
                    const ull Bv = *(const ull*)(rp + 2);
                    const ull Cv = *(const ull*)(rp + 4);
                    PA[rr] = A; PB[rr] = Bv; PC[rr] = Cv;
                    PAB[rr] = hilo(A, Bv); PBC[rr] = hilo(Bv, Cv);
                }
                const int wb = co * 432 + (cc * 3 + c) * 9;
#pragma unroll
                for (int ky = 0; ky < 3; ++ky)
#pragma unroll
                    for (int kx = 0; kx < 3; ++kx) {
                        const ull w = sw2[wb + ky * 3 + kx];
                        ffma2(a0, kx == 0 ? PA[ky] : (kx == 1 ? PAB[ky] : PB[ky]), w);
                        ffma2(a1, kx == 0 ? PB[ky] : (kx == 1 ? PBC[ky] : PC[ky]), w);
                    }
            }
        }
        __syncthreads();
    }

    // ---- epilogue: activations -> sraw (+ v -> out) ----
    if (active) {
        const float bias = (co < 8) ? b2o[co] : b2g[0];
        float v[4];
        upkf2(a0, v[0], v[1]);
        upkf2(a1, v[2], v[3]);
#pragma unroll
        for (int p = 0; p < 4; ++p) {
            if (p >= nvalid) continue;
            const float raw = v[p] + bias;
            if (co < 8) {
                const float t = fast_tanh(raw);
                sraw[co * 252 + row * 84 + tc + p] = t;
                out[OUT_V_OFF + (b * 8 + co) * HW + (r0 + row) * WL + tc + p] = t;
            } else {
                sraw[8 * 252 + row * 84 + tc + p] = fast_sigmoid(raw);
            }
        }
    }
    __syncthreads();

    // ---- phase 2: masks + geometry + g_up ----
    if (tid < 243) {
        const int rowl = tid / 81;
        const int xx   = tid - rowl * 81;
        const int sb   = rowl * 84 + xx;

        const float p0 = sraw[0 * 252 + sb] - sraw[4 * 252 + sb];
        const float p1 = sraw[1 * 252 + sb] - sraw[5 * 252 + sb];
        const float p2 = sraw[2 * 252 + sb] - sraw[6 * 252 + sb];
        const float p3 = sraw[3 * 252 + sb] - sraw[7 * 252 + sb];
        const float g  = sraw[8 * 252 + sb];

        const float k00 = (p0 + p1 + p2) * 0.125f;
        const float k01 = (p1 + p2 + p3) * 0.125f;
        const float k02 = (-p0 + p2 + p3) * 0.125f;
        const float k10 = (p0 + p1 - p3) * 0.125f;

        float kb[9];
        kb[0] = k00;  kb[1] = k01;  kb[2] = k02;
        kb[3] = k10;  kb[4] = 2.5f; kb[5] = -k10;
        kb[6] = -k02; kb[7] = -k01; kb[8] = -k00;

        float mx = kb[0];
#pragma unroll
        for (int n = 1; n < 9; ++n) mx = fmaxf(mx, kb[n]);
        float e[9], se = 0.f;
#pragma unroll
        for (int n = 0; n < 9; ++n) { e[n] = __expf((kb[n] - mx) * 2.0f); se += e[n]; }
        const float inv_se = __fdividef(1.0f, se);

        const float mean = 2.5f / 9.0f;
        float sa = 0.f;
#pragma unroll
        for (int n = 0; n < 9; ++n) sa += fabsf(kb[n] - mean);
        const float hinv = __fdividef(1.0f, sa + 1e-8f);

        const float lam = 0.15f * (1.0f - g);
        const float tbg = tanhf(beta[0]) * g;

        float w[12];
#pragma unroll
        for (int n = 0; n < 9; ++n) w[n] = lam * e[n] * inv_se + tbg * (kb[n] - mean) * hinv;
        w[9]  = 1.0f - lam;
        w[10] = g;
        w[11] = 0.f;

        float* dm = &smask[tid * 12];
        ((float4*)dm)[0] = make_float4(w[0], w[1], w[2], w[3]);
        ((float4*)dm)[1] = make_float4(w[4], w[5], w[6], w[7]);
        ((float4*)dm)[2] = make_float4(w[8], w[9], w[10], w[11]);

        const int y = r0 + rowl;
        const float4 gq = make_float4(g, g, g, g);
        float* gd = &out[OUT_G_OFF + b * HWO + (y * 4) * WOUTX + xx * 4];
#pragma unroll
        for (int jy = 0; jy < 4; ++jy) *(float4*)(gd + jy * WOUTX) = gq;
    } else if (tid >= 288 && tid < 369) {
        const int q = tid - 288;
        float w3[4][3];
#pragma unroll
        for (int j = 0; j < 4; ++j) {
            const float f = (float)(q * 4 + j) * sc;
            int i0 = (int)f; if (i0 > 79) i0 = 79;
            const float w = f - (float)i0;
            const bool lo = (i0 != q);
            w3[j][0] = lo ? (1.f - w) : 0.f;
            w3[j][1] = lo ? w : (1.f - w);
            w3[j][2] = lo ? 0.f : w;
        }
#pragma unroll
        for (int p = 0; p < 2; ++p)
#pragma unroll
            for (int j = 0; j < 3; ++j)
                swx[q * 6 + p * 3 + j] = pkf2(w3[2 * p][j], w3[2 * p + 1][j]);
    } else if (tid >= 384 && tid < 396) {
        const int t2 = tid - 384;
        const int rowl = t2 / 4, jy = t2 - (t2 / 4) * 4;
        const int q = r0 + rowl;
        const float f = (float)(q * 4 + jy) * sc;
        int i0 = (int)f; if (i0 > 79) i0 = 79;
        const float w = f - (float)i0;
        const bool lo = (i0 != q);
        const float t0 = lo ? (1.f - w) : 0.f;
        const float t1 = lo ? w : (1.f - w);
        const float t2f = lo ? 0.f : w;
        swy[(rowl * 4 + jy) * 3 + 0] = pkf2(t0, t0);
        swy[(rowl * 4 + jy) * 3 + 1] = pkf2(t1, t1);
        swy[(rowl * 4 + jy) * 3 + 2] = pkf2(t2f, t2f);
    }
    __syncthreads();

    // ---- phase 3: upsample ----
    for (int t = tid; t < 5103; t += 576) {
        const int ch   = t / 243;
        const int pxl  = t - ch * 243;
        const int rowl = pxl / 81;
        const int xx   = pxl - rowl * 81;
        const int y    = r0 + rowl;

        const float* wsrc = &smask[pxl * 12];
        const float4 m0 = ((const float4*)wsrc)[0];
        const float4 m1 = ((const float4*)wsrc)[1];
        const float4 m2 = ((const float4*)wsrc)[2];
        const float wm[9] = {m0.x, m0.y, m0.z, m0.w, m1.x, m1.y, m1.z, m1.w, m2.x};
        const float oml = m2.y;
        const ull oml2 = pkf2(oml, oml);

        const int ym = (y == 0) ? 1 : y - 1,   ypl = (y == HL - 1) ? HL - 2 : y + 1;
        const int xm = (xx == 0) ? 1 : xx - 1, xpl = (xx == WL - 1) ? WL - 2 : xx + 1;
        const int ry[3] = {ym, y, ypl};
        const int rx[3] = {xm, xx, xpl};

        const float* xb = x + (b * CIN + ch) * HW;
        float tv[3][3];
#pragma unroll
        for (int i = 0; i < 3; ++i)
#pragma unroll
            for (int j = 0; j < 3; ++j)
                tv[i][j] = xb[ry[i] * WL + rx[j]];

        float yc = 0.f;
#pragma unroll
        for (int i = 0; i < 3; ++i)
#pragma unroll
            for (int j = 0; j < 3; ++j)
                yc += tv[i][j] * wm[i * 3 + j];
        const ull yc2 = pkf2(yc, yc);

        ull wxp[6];
#pragma unroll
        for (int i = 0; i < 6; ++i) wxp[i] = swx[xx * 6 + i];

        ull cvp[3][2];
#pragma unroll
        for (int i = 0; i < 3; ++i) { cvp[i][0] = 0ULL; cvp[i][1] = 0ULL; }
#pragma unroll
        for (int i = 0; i < 3; ++i)
#pragma unroll
            for (int j = 0; j < 3; ++j) {
                const ull td = pkf2(tv[i][j], tv[i][j]);
                ffma2(cvp[i][0], td, wxp[j]);
                ffma2(cvp[i][1], td, wxp[3 + j]);
            }

        float* dst = &out[(b * CIN + ch) * HWO + (y * 4) * WOUTX + xx * 4];
#pragma unroll
        for (int jy = 0; jy < 4; ++jy) {
            ull bil0 = 0ULL, bil1 = 0ULL;
#pragma unroll
            for (int i = 0; i < 3; ++i) {
                const ull wy = swy[(rowl * 4 + jy) * 3 + i];
                ffma2(bil0, cvp[i][0], wy);
                ffma2(bil1, cvp[i][1], wy);
            }
            ull rr0 = yc2, rr1 = yc2;
            ffma2(rr0, bil0, oml2);
            ffma2(rr1, bil1, oml2);
            float o0, o1, o2, o3;
            upkf2(rr0, o0, o1);
            upkf2(rr1, o2, o3);
            *(float4*)(dst + jy * WOUTX) = make_float4(o0, o1, o2, o3);
        }
    }
}

// ==========================================================================
extern "C" void kernel_launch(void* const* d_in, const int* in_sizes, int n_in,
                              void* d_out, int out_size)
{
    const float* x    = (const float*)d_in[0];
    const float* w1o  = (const float*)d_in[1];
    const float* b1o  = (const float*)d_in[2];
    const float* w2o  = (const float*)d_in[3];
    const float* b2o  = (const float*)d_in[4];
    const float* w1g  = (const float*)d_in[5];
    const float* b1g  = (const float*)d_in[6];
    const float* w2g  = (const float*)d_in[7];
    const float* b2g  = (const float*)d_in[8];
    const float* beta = (const float*)d_in[9];
    float* out = (float*)d_out;

    pad_kernel<<<dim3(27, CIN), dim3(81, 3)>>>(x);
    conv1_kernel<<<dim3(3, 24, Bn), 192>>>(w1o, b1o, w1g, b1g);
    conv2fused_kernel<<<dim3(27, Bn), 576>>>(w2o, b2o, w2g, b2g, beta, x, out);
}

// round 15
// speedup vs baseline: 1.0726x; 1.0004x over previous
#include <cuda_runtime.h>
#include <math.h>

typedef unsigned long long ull;

// ---------------- problem constants ----------------
#define Bn    4
#define CIN   21
#define HL    81
#define WL    81
#define HW    6561
#define HWO   104976
#define WOUTX 324
#define XPW   88
#define XPP   7304        // 83*88

#define OUT_V_OFF 8817984
#define OUT_G_OFF 9027936

// ---------------- scratch (zero-init BSS: halos stay zero forever) --------
__device__ float g_xpad[Bn * CIN * XPP];
__device__ float g_hidden[Bn * 96 * XPP];

// ---------------- packed fp32x2 helpers ----------------
__device__ __forceinline__ ull pkf2(float lo, float hi) {
    ull r; asm("mov.b64 %0, {%1,%2};" : "=l"(r) : "f"(lo), "f"(hi)); return r;
}
__device__ __forceinline__ void upkf2(ull v, float& lo, float& hi) {
    asm("mov.b64 {%0,%1}, %2;" : "=f"(lo), "=f"(hi) : "l"(v));
}
__device__ __forceinline__ void ffma2(ull& d, ull a, ull b) {
    asm("fma.rn.f32x2 %0, %1, %2, %0;" : "+l"(d) : "l"(a), "l"(b));
}
__device__ __forceinline__ ull hilo(ull a, ull b) {
    float al, ah, bl, bh; upkf2(a, al, ah); upkf2(b, bl, bh); return pkf2(ah, bl);
}

__device__ __forceinline__ float fast_tanh(float x) {
    const float e2 = __expf(2.0f * x);
    return 1.0f - __fdividef(2.0f, e2 + 1.0f);
}
__device__ __forceinline__ float fast_sigmoid(float x) {
    return __fdividef(1.0f, 1.0f + __expf(-x));
}

// ==========================================================================
// Kernel 0: interior-only copy x -> xpad, 2 rows x 4 batches (MLP 8).
// grid (14, 21); block (81, 3).
// ==========================================================================
__global__ __launch_bounds__(243) void pad_kernel(const float* __restrict__ x)
{
    const int c    = blockIdx.y;
    const int row0 = blockIdx.x * 6 + threadIdx.y;      // rows row0, row0+3
    const int col  = threadIdx.x;
#pragma unroll
    for (int rr = 0; rr < 2; ++rr) {
        const int row = row0 + rr * 3;
        if (row >= HL) continue;
        const int srel = row * WL + col;
        const int drel = (row + 1) * XPW + col + 1;
#pragma unroll
        for (int b = 0; b < Bn; ++b)
            g_xpad[(b * CIN + c) * XPP + drel] = x[(b * CIN + c) * HW + srel];
    }
}

// ==========================================================================
// Kernel 1: conv1 (21 -> 96), ReLU. R13 double-buffered version (exact).
// grid (3, 24, Bn); block 192 (189 active). 3 rows x 4 px x 4 co / thread.
// ==========================================================================
#define C1_F4 (3 * 29 * 22)
__global__ __launch_bounds__(192) void conv1_kernel(
    const float* __restrict__ w1o, const float* __restrict__ b1o,
    const float* __restrict__ w1g, const float* __restrict__ b1g)
{
    __shared__ __align__(16) float sx[2][3 * 29 * XPW];
    __shared__ ull sw2[4 * 189];

    const int tile = blockIdx.x;
    const int cg   = blockIdx.y;
    const int b    = blockIdx.z;
    const int r0   = tile * 27;
    const int tid  = threadIdx.x;

    for (int i = tid; i < 4 * 189; i += 192) {
        const int co = i / 189, j = i - co * 189;
        const int co_out = cg * 4 + co;
        const float w = (co_out < 48) ? w1o[co_out * 189 + j] : w1g[(co_out - 48) * 189 + j];
        sw2[i] = pkf2(w, w);
    }

    const bool active = tid < 189;
    const int trp = active ? (tid / 21) : 0;
    const int tc  = active ? ((tid - trp * 21) * 4) : 0;
    const int trp3 = trp * 3;
    const int nvalid = (tc == 80) ? 1 : 4;

    {
        const float4* src = (const float4*)g_xpad;
        for (int i = tid; i < C1_F4; i += 192) {
            const int c  = i / 638;
            const int rm = i - c * 638;
            const int lr = rm / 22;
            const int f4 = rm - lr * 22;
            ((float4*)sx[0])[(c * 29 + lr) * 22 + f4] =
                src[((b * CIN + c) * XPP + (r0 + lr) * XPW) / 4 + f4];
        }
    }
    __syncthreads();

    ull acc[4][3][2];
#pragma unroll
    for (int co = 0; co < 4; ++co)
#pragma unroll
        for (int r = 0; r < 3; ++r) { acc[co][r][0] = 0ULL; acc[co][r][1] = 0ULL; }

    for (int cc = 0; cc < 7; ++cc) {
        const int cur = cc & 1;
        if (cc < 6) {
            const float4* src = (const float4*)g_xpad;
#pragma unroll 2
            for (int i = tid; i < C1_F4; i += 192) {
                const int c  = i / 638;
                const int rm = i - c * 638;
                const int lr = rm / 22;
                const int f4 = rm - lr * 22;
                ((float4*)sx[cur ^ 1])[(c * 29 + lr) * 22 + f4] =
                    src[((b * CIN + (cc + 1) * 3 + c) * XPP + (r0 + lr) * XPW) / 4 + f4];
            }
        }

        if (active) {
#pragma unroll
            for (int c = 0; c < 3; ++c) {
                ull PA[5], PAB[5], PB[5], PBC[5], PC[5];
#pragma unroll
                for (int rr = 0; rr < 5; ++rr) {
                    const float* rp = &sx[cur][(c * 29 + trp3 + rr) * XPW + tc];
                    const ull A  = *(const ull*)rp;
                    const ull Bv = *(const ull*)(rp + 2);
                    const ull Cv = *(const ull*)(rp + 4);
                    PA[rr] = A; PB[rr] = Bv; PC[rr] = Cv;
                    PAB[rr] = hilo(A, Bv); PBC[rr] = hilo(Bv, Cv);
                }
                const int wb = (cc * 3 + c) * 9;
#pragma unroll
                for (int ky = 0; ky < 3; ++ky)
#pragma unroll
                    for (int kx = 0; kx < 3; ++kx)
#pragma unroll
                        for (int co = 0; co < 4; ++co) {
                            const ull w = sw2[co * 189 + wb + ky * 3 + kx];
#pragma unroll
                            for (int r = 0; r < 3; ++r) {
                                const int rw = r + ky;
                                ffma2(acc[co][r][0],
                                      kx == 0 ? PA[rw] : (kx == 1 ? PAB[rw] : PB[rw]), w);
                                ffma2(acc[co][r][1],
                                      kx == 0 ? PB[rw] : (kx == 1 ? PBC[rw] : PC[rw]), w);
                            }
                        }
            }
        }
        if (cc < 6) __syncthreads();
    }

    if (active) {
#pragma unroll
        for (int co = 0; co < 4; ++co) {
            const int co_out = cg * 4 + co;
            const float bias = (co_out < 48) ? b1o[co_out] : b1g[co_out - 48];
#pragma unroll
            for (int r = 0; r < 3; ++r) {
                const int orow = r0 + trp3 + r;
                float* dst = &g_hidden[(b * 96 + co_out) * XPP + (orow + 1) * XPW + tc + 1];
                float v[4];
                upkf2(acc[co][r][0], v[0], v[1]);
                upkf2(acc[co][r][1], v[2], v[3]);
#pragma unroll
                for (int p = 0; p < 4; ++p)
                    if (p < nvalid) dst[p] = fmaxf(v[p] + bias, 0.f);
            }
        }
    }
}

// ==========================================================================
// Kernel 2 (FUSED): conv2 heads + mask + upsample. R13 version (exact).
// ==========================================================================
#define C2F_F4 660
__global__ __launch_bounds__(576) void conv2fused_kernel(
    const float* __restrict__ w2o, const float* __restrict__ b2o,
    const float* __restrict__ w2g, const float* __restrict__ b2g,
    const float* __restrict__ beta, const float* __restrict__ x,
    float* __restrict__ out)
{
    __shared__ __align__(16) unsigned char smem[52224];
    float* sx0   = (float*)smem;
    float* sx1   = (float*)(smem + 10560);
    float* sraw  = (float*)smem;                        // overlay sx0
    ull*   sw2   = (ull*)(smem + 21120);
    float* smask = (float*)(smem + 21120);              // overlay sw2
    ull*   swx   = (ull*)(smem + 21120 + 11664);
    ull*   swy   = (ull*)(smem + 21120 + 11664 + 3888);

    const int tile = blockIdx.x;
    const int b    = blockIdx.y;
    const int r0   = tile * 3;
    const int tid  = threadIdx.x;
    const float sc = 80.0f / 323.0f;

    for (int i = tid; i < 9 * 432; i += 576) {
        const int co = i / 432, j = i - co * 432;
        const float w = (co < 8) ? w2o[co * 432 + j] : w2g[j];
        sw2[i] = pkf2(w, w);
    }

    const bool active = tid < 567;
    const int co  = active ? (tid / 63) : 0;
    const int s   = active ? (tid - co * 63) : 0;
    const int row = s / 21;
    const int tc  = (s - row * 21) * 4;
    const int nvalid = (tc == 80) ? 1 : 4;
    const int csel = (co == 8) ? 3 : 0;

    {
        const float4* src = (const float4*)g_hidden;
        for (int i = tid; i < C2F_F4; i += 576) {
            const int c  = i / 110;
            const int rm = i - c * 110;
            const int lr = rm / 22;
            const int f4 = rm - lr * 22;
            const int ch = (c < 3) ? c : (48 + c - 3);
            ((float4*)sx0)[(c * 5 + lr) * 22 + f4] =
                src[((b * 96 + ch) * XPP + (r0 + lr) * XPW) / 4 + f4];
        }
    }
    __syncthreads();

    ull a0 = 0ULL, a1 = 0ULL;

    for (int cc = 0; cc < 16; ++cc) {
        float* cursx = (cc & 1) ? sx1 : sx0;
        float* nxtsx = (cc & 1) ? sx0 : sx1;

        if (cc < 15) {
            const float4* src = (const float4*)g_hidden;
            for (int i = tid; i < C2F_F4; i += 576) {
                const int c  = i / 110;
                const int rm = i - c * 110;
                const int lr = rm / 22;
                const int f4 = rm - lr * 22;
                const int ch = (c < 3) ? ((cc + 1) * 3 + c) : (48 + (cc + 1) * 3 + (c - 3));
                ((float4*)nxtsx)[(c * 5 + lr) * 22 + f4] =
                    src[((b * 96 + ch) * XPP + (r0 + lr) * XPW) / 4 + f4];
            }
        }

        if (active) {
#pragma unroll
            for (int c = 0; c < 3; ++c) {
                ull PA[3], PAB[3], PB[3], PBC[3], PC[3];
#pragma unroll
                for (int rr = 0; rr < 3; ++rr) {
                    const float* rp = &cursx[((csel + c) * 5 + row + rr) * XPW + tc];
                    const ull A  = *(const ull*)rp;
                    const ull Bv = *(const ull*)(rp + 2);
                    const ull Cv = *(const ull*)(rp + 4);
                    PA[rr] = A; PB[rr] = Bv; PC[rr] = Cv;
                    PAB[rr] = hilo(A, Bv); PBC[rr] = hilo(Bv, Cv);
                }
                const int wb = co * 432 + (cc * 3 + c) * 9;
#pragma unroll
                for (int ky = 0; ky < 3; ++ky)
#pragma unroll
                    for (int kx = 0; kx < 3; ++kx) {
                        const ull w = sw2[wb + ky * 3 + kx];
                        ffma2(a0, kx == 0 ? PA[ky] : (kx == 1 ? PAB[ky] : PB[ky]), w);
                        ffma2(a1, kx == 0 ? PB[ky] : (kx == 1 ? PBC[ky] : PC[ky]), w);
                    }
            }
        }
        __syncthreads();
    }

    // ---- epilogue: activations -> sraw (+ v -> out) ----
    if (active) {
        const float bias = (co < 8) ? b2o[co] : b2g[0];
        float v[4];
        upkf2(a0, v[0], v[1]);
        upkf2(a1, v[2], v[3]);
#pragma unroll
        for (int p = 0; p < 4; ++p) {
            if (p >= nvalid) continue;
            const float raw = v[p] + bias;
            if (co < 8) {
                const float t = fast_tanh(raw);
                sraw[co * 252 + row * 84 + tc + p] = t;
                out[OUT_V_OFF + (b * 8 + co) * HW + (r0 + row) * WL + tc + p] = t;
            } else {
                sraw[8 * 252 + row * 84 + tc + p] = fast_sigmoid(raw);
            }
        }
    }
    __syncthreads();

    // ---- phase 2: masks + geometry + g_up ----
    if (tid < 243) {
        const int rowl = tid / 81;
        const int xx   = tid - rowl * 81;
        const int sb   = rowl * 84 + xx;

        const float p0 = sraw[0 * 252 + sb] - sraw[4 * 252 + sb];
        const float p1 = sraw[1 * 252 + sb] - sraw[5 * 252 + sb];
        const float p2 = sraw[2 * 252 + sb] - sraw[6 * 252 + sb];
        const float p3 = sraw[3 * 252 + sb] - sraw[7 * 252 + sb];
        const float g  = sraw[8 * 252 + sb];

        const float k00 = (p0 + p1 + p2) * 0.125f;
        const float k01 = (p1 + p2 + p3) * 0.125f;
        const float k02 = (-p0 + p2 + p3) * 0.125f;
        const float k10 = (p0 + p1 - p3) * 0.125f;

        float kb[9];
        kb[0] = k00;  kb[1] = k01;  kb[2] = k02;
        kb[3] = k10;  kb[4] = 2.5f; kb[5] = -k10;
        kb[6] = -k02; kb[7] = -k01; kb[8] = -k00;

        float mx = kb[0];
#pragma unroll
        for (int n = 1; n < 9; ++n) mx = fmaxf(mx, kb[n]);
        float e[9], se = 0.f;
#pragma unroll
        for (int n = 0; n < 9; ++n) { e[n] = __expf((kb[n] - mx) * 2.0f); se += e[n]; }
        const float inv_se = __fdividef(1.0f, se);

        const float mean = 2.5f / 9.0f;
        float sa = 0.f;
#pragma unroll
        for (int n = 0; n < 9; ++n) sa += fabsf(kb[n] - mean);
        const float hinv = __fdividef(1.0f, sa + 1e-8f);

        const float lam = 0.15f * (1.0f - g);
        const float tbg = tanhf(beta[0]) * g;

        float w[12];
#pragma unroll
        for (int n = 0; n < 9; ++n) w[n] = lam * e[n] * inv_se + tbg * (kb[n] - mean) * hinv;
        w[9]  = 1.0f - lam;
        w[10] = g;
        w[11] = 0.f;

        float* dm = &smask[tid * 12];
        ((float4*)dm)[0] = make_float4(w[0], w[1], w[2], w[3]);
        ((float4*)dm)[1] = make_float4(w[4], w[5], w[6], w[7]);
        ((float4*)dm)[2] = make_float4(w[8], w[9], w[10], w[11]);

        const int y = r0 + rowl;
        const float4 gq = make_float4(g, g, g, g);
        float* gd = &out[OUT_G_OFF + b * HWO + (y * 4) * WOUTX + xx * 4];
#pragma unroll
        for (int jy = 0; jy < 4; ++jy) *(float4*)(gd + jy * WOUTX) = gq;
    } else if (tid >= 288 && tid < 369) {
        const int q = tid - 288;
        float w3[4][3];
#pragma unroll
        for (int j = 0; j < 4; ++j) {
            const float f = (float)(q * 4 + j) * sc;
            int i0 = (int)f; if (i0 > 79) i0 = 79;
            const float w = f - (float)i0;
            const bool lo = (i0 != q);
            w3[j][0] = lo ? (1.f - w) : 0.f;
            w3[j][1] = lo ? w : (1.f - w);
            w3[j][2] = lo ? 0.f : w;
        }
#pragma unroll
        for (int p = 0; p < 2; ++p)
#pragma unroll
            for (int j = 0; j < 3; ++j)
                swx[q * 6 + p * 3 + j] = pkf2(w3[2 * p][j], w3[2 * p + 1][j]);
    } else if (tid >= 384 && tid < 396) {
        const int t2 = tid - 384;
        const int rowl = t2 / 4, jy = t2 - (t2 / 4) * 4;
        const int q = r0 + rowl;
        const float f = (float)(q * 4 + jy) * sc;
        int i0 = (int)f; if (i0 > 79) i0 = 79;
        const float w = f - (float)i0;
        const bool lo = (i0 != q);
        const float t0 = lo ? (1.f - w) : 0.f;
        const float t1 = lo ? w : (1.f - w);
        const float t2f = lo ? 0.f : w;
        swy[(rowl * 4 + jy) * 3 + 0] = pkf2(t0, t0);
        swy[(rowl * 4 + jy) * 3 + 1] = pkf2(t1, t1);
        swy[(rowl * 4 + jy) * 3 + 2] = pkf2(t2f, t2f);
    }
    __syncthreads();

    // ---- phase 3: upsample ----
    for (int t = tid; t < 5103; t += 576) {
        const int ch   = t / 243;
        const int pxl  = t - ch * 243;
        const int rowl = pxl / 81;
        const int xx   = pxl - rowl * 81;
        const int y    = r0 + rowl;

        const float* wsrc = &smask[pxl * 12];
        const float4 m0 = ((const float4*)wsrc)[0];
        const float4 m1 = ((const float4*)wsrc)[1];
        const float4 m2 = ((const float4*)wsrc)[2];
        const float wm[9] = {m0.x, m0.y, m0.z, m0.w, m1.x, m1.y, m1.z, m1.w, m2.x};
        const float oml = m2.y;
        const ull oml2 = pkf2(oml, oml);

        const int ym = (y == 0) ? 1 : y - 1,   ypl = (y == HL - 1) ? HL - 2 : y + 1;
        const int xm = (xx == 0) ? 1 : xx - 1, xpl = (xx == WL - 1) ? WL - 2 : xx + 1;
        const int ry[3] = {ym, y, ypl};
        const int rx[3] = {xm, xx, xpl};

        const float* xb = x + (b * CIN + ch) * HW;
        float tv[3][3];
#pragma unroll
        for (int i = 0; i < 3; ++i)
#pragma unroll
            for (int j = 0; j < 3; ++j)
                tv[i][j] = xb[ry[i] * WL + rx[j]];

        float yc = 0.f;
#pragma unroll
        for (int i = 0; i < 3; ++i)
#pragma unroll
            for (int j = 0; j < 3; ++j)
                yc += tv[i][j] * wm[i * 3 + j];
        const ull yc2 = pkf2(yc, yc);

        ull wxp[6];
#pragma unroll
        for (int i = 0; i < 6; ++i) wxp[i] = swx[xx * 6 + i];

        ull cvp[3][2];
#pragma unroll
        for (int i = 0; i < 3; ++i) { cvp[i][0] = 0ULL; cvp[i][1] = 0ULL; }
#pragma unroll
        for (int i = 0; i < 3; ++i)
#pragma unroll
            for (int j = 0; j < 3; ++j) {
                const ull td = pkf2(tv[i][j], tv[i][j]);
                ffma2(cvp[i][0], td, wxp[j]);
                ffma2(cvp[i][1], td, wxp[3 + j]);
            }

        float* dst = &out[(b * CIN + ch) * HWO + (y * 4) * WOUTX + xx * 4];
#pragma unroll
        for (int jy = 0; jy < 4; ++jy) {
            ull bil0 = 0ULL, bil1 = 0ULL;
#pragma unroll
            for (int i = 0; i < 3; ++i) {
                const ull wy = swy[(rowl * 4 + jy) * 3 + i];
                ffma2(bil0, cvp[i][0], wy);
                ffma2(bil1, cvp[i][1], wy);
            }
            ull rr0 = yc2, rr1 = yc2;
            ffma2(rr0, bil0, oml2);
            ffma2(rr1, bil1, oml2);
            float o0, o1, o2, o3;
            upkf2(rr0, o0, o1);
            upkf2(rr1, o2, o3);
            *(float4*)(dst + jy * WOUTX) = make_float4(o0, o1, o2, o3);
        }
    }
}

// ==========================================================================
extern "C" void kernel_launch(void* const* d_in, const int* in_sizes, int n_in,
                              void* d_out, int out_size)
{
    const float* x    = (const float*)d_in[0];
    const float* w1o  = (const float*)d_in[1];
    const float* b1o  = (const float*)d_in[2];
    const float* w2o  = (const float*)d_in[3];
    const float* b2o  = (const float*)d_in[4];
    const float* w1g  = (const float*)d_in[5];
    const float* b1g  = (const float*)d_in[6];
    const float* w2g  = (const float*)d_in[7];
    const float* b2g  = (const float*)d_in[8];
    const float* beta = (const float*)d_in[9];
    float* out = (float*)d_out;

    pad_kernel<<<dim3(14, CIN), dim3(81, 3)>>>(x);
    conv1_kernel<<<dim3(3, 24, Bn), 192>>>(w1o, b1o, w1g, b1g);
    conv2fused_kernel<<<dim3(27, Bn), 576>>>(w2o, b2o, w2g, b2g, beta, x, out);
}

// round 16
// speedup vs baseline: 1.1496x; 1.0718x over previous
#include <cuda_runtime.h>
#include <math.h>

typedef unsigned long long ull;

// ---------------- problem constants ----------------
#define Bn    4
#define CIN   21
#define HL    81
#define WL    81
#define HW    6561
#define HWO   104976
#define WOUTX 324
#define XPW   88
#define XPP   7304        // 83*88

#define OUT_V_OFF 8817984
#define OUT_G_OFF 9027936

// ---------------- scratch (zero-init BSS: halos stay zero forever) --------
__device__ float g_xpad[Bn * CIN * XPP];
__device__ float g_hidden[Bn * 96 * XPP];

// ---------------- packed fp32x2 helpers ----------------
__device__ __forceinline__ ull pkf2(float lo, float hi) {
    ull r; asm("mov.b64 %0, {%1,%2};" : "=l"(r) : "f"(lo), "f"(hi)); return r;
}
__device__ __forceinline__ void upkf2(ull v, float& lo, float& hi) {
    asm("mov.b64 {%0,%1}, %2;" : "=f"(lo), "=f"(hi) : "l"(v));
}
__device__ __forceinline__ void ffma2(ull& d, ull a, ull b) {
    asm("fma.rn.f32x2 %0, %1, %2, %0;" : "+l"(d) : "l"(a), "l"(b));
}
__device__ __forceinline__ ull hilo(ull a, ull b) {
    float al, ah, bl, bh; upkf2(a, al, ah); upkf2(b, bl, bh); return pkf2(ah, bl);
}

__device__ __forceinline__ float fast_tanh(float x) {
    const float e2 = __expf(2.0f * x);
    return 1.0f - __fdividef(2.0f, e2 + 1.0f);
}
__device__ __forceinline__ float fast_sigmoid(float x) {
    return __fdividef(1.0f, 1.0f + __expf(-x));
}

// ==========================================================================
// Kernel 0: interior-only copy x -> xpad, 4 batches per thread (MLP 4).
// grid (27, 21); block (81, 3).   [R13 version, measured 4.5us]
// ==========================================================================
__global__ __launch_bounds__(243) void pad_kernel(const float* __restrict__ x)
{
    const int c   = blockIdx.y;
    const int row = blockIdx.x * 3 + threadIdx.y;
    const int col = threadIdx.x;
    const int srel = row * WL + col;
    const int drel = (row + 1) * XPW + col + 1;
#pragma unroll
    for (int b = 0; b < Bn; ++b)
        g_xpad[(b * CIN + c) * XPP + drel] = x[(b * CIN + c) * HW + srel];
}

// ==========================================================================
// probe: empty kernel appended so ncu's skip-5 capture lands on conv1.
// ==========================================================================
__global__ void probe_kernel() {}

// ==========================================================================
// Kernel 1: conv1 (21 -> 96), ReLU. R13 double-buffered; staging fully
// unrolled (MLP 10). Accumulation order unchanged -> bit-identical.
// grid (3, 24, Bn); block 192 (189 active).
// ==========================================================================
#define C1_F4 (3 * 29 * 22)
__global__ __launch_bounds__(192) void conv1_kernel(
    const float* __restrict__ w1o, const float* __restrict__ b1o,
    const float* __restrict__ w1g, const float* __restrict__ b1g)
{
    __shared__ __align__(16) float sx[2][3 * 29 * XPW];
    __shared__ ull sw2[4 * 189];

    const int tile = blockIdx.x;
    const int cg   = blockIdx.y;
    const int b    = blockIdx.z;
    const int r0   = tile * 27;
    const int tid  = threadIdx.x;

    for (int i = tid; i < 4 * 189; i += 192) {
        const int co = i / 189, j = i - co * 189;
        const int co_out = cg * 4 + co;
        const float w = (co_out < 48) ? w1o[co_out * 189 + j] : w1g[(co_out - 48) * 189 + j];
        sw2[i] = pkf2(w, w);
    }

    const bool active = tid < 189;
    const int trp = active ? (tid / 21) : 0;
    const int tc  = active ? ((tid - trp * 21) * 4) : 0;
    const int trp3 = trp * 3;
    const int nvalid = (tc == 80) ? 1 : 4;

    {
        const float4* src = (const float4*)g_xpad;
#pragma unroll
        for (int k = 0; k < 10; ++k) {
            const int i = tid + k * 192;
            if (i < C1_F4) {
                const int c  = i / 638;
                const int rm = i - c * 638;
                const int lr = rm / 22;
                const int f4 = rm - lr * 22;
                ((float4*)sx[0])[(c * 29 + lr) * 22 + f4] =
                    src[((b * CIN + c) * XPP + (r0 + lr) * XPW) / 4 + f4];
            }
        }
    }
    __syncthreads();

    ull acc[4][3][2];
#pragma unroll
    for (int co = 0; co < 4; ++co)
#pragma unroll
        for (int r = 0; r < 3; ++r) { acc[co][r][0] = 0ULL; acc[co][r][1] = 0ULL; }

    for (int cc = 0; cc < 7; ++cc) {
        const int cur = cc & 1;
        if (cc < 6) {
            const float4* src = (const float4*)g_xpad;
#pragma unroll
            for (int k = 0; k < 10; ++k) {
                const int i = tid + k * 192;
                if (i < C1_F4) {
                    const int c  = i / 638;
                    const int rm = i - c * 638;
                    const int lr = rm / 22;
                    const int f4 = rm - lr * 22;
                    ((float4*)sx[cur ^ 1])[(c * 29 + lr) * 22 + f4] =
                        src[((b * CIN + (cc + 1) * 3 + c) * XPP + (r0 + lr) * XPW) / 4 + f4];
                }
            }
        }

        if (active) {
#pragma unroll
            for (int c = 0; c < 3; ++c) {
                ull PA[5], PAB[5], PB[5], PBC[5], PC[5];
#pragma unroll
                for (int rr = 0; rr < 5; ++rr) {
                    const float* rp = &sx[cur][(c * 29 + trp3 + rr) * XPW + tc];
                    const ull A  = *(const ull*)rp;
                    const ull Bv = *(const ull*)(rp + 2);
                    const ull Cv = *(const ull*)(rp + 4);
                    PA[rr] = A; PB[rr] = Bv; PC[rr] = Cv;
                    PAB[rr] = hilo(A, Bv); PBC[rr] = hilo(Bv, Cv);
                }
                const int wb = (cc * 3 + c) * 9;
#pragma unroll
                for (int ky = 0; ky < 3; ++ky)
#pragma unroll
                    for (int kx = 0; kx < 3; ++kx)
#pragma unroll
                        for (int co = 0; co < 4; ++co) {
                            const ull w = sw2[co * 189 + wb + ky * 3 + kx];
#pragma unroll
                            for (int r = 0; r < 3; ++r) {
                                const int rw = r + ky;
                                ffma2(acc[co][r][0],
                                      kx == 0 ? PA[rw] : (kx == 1 ? PAB[rw] : PB[rw]), w);
                                ffma2(acc[co][r][1],
                                      kx == 0 ? PB[rw] : (kx == 1 ? PBC[rw] : PC[rw]), w);
                            }
                        }
            }
        }
        if (cc < 6) __syncthreads();
    }

    if (active) {
#pragma unroll
        for (int co = 0; co < 4; ++co) {
            const int co_out = cg * 4 + co;
            const float bias = (co_out < 48) ? b1o[co_out] : b1g[co_out - 48];
#pragma unroll
            for (int r = 0; r < 3; ++r) {
                const int orow = r0 + trp3 + r;
                float* dst = &g_hidden[(b * 96 + co_out) * XPP + (orow + 1) * XPW + tc + 1];
                float v[4];
                upkf2(acc[co][r][0], v[0], v[1]);
                upkf2(acc[co][r][1], v[2], v[3]);
#pragma unroll
                for (int p = 0; p < 4; ++p)
                    if (p < nvalid) dst[p] = fmaxf(v[p] + bias, 0.f);
            }
        }
    }
}

// ==========================================================================
// Kernel 2 (FUSED): conv2 heads + mask + upsample. R13 version (exact).
// ==========================================================================
#define C2F_F4 660
__global__ __launch_bounds__(576) void conv2fused_kernel(
    const float* __restrict__ w2o, const float* __restrict__ b2o,
    const float* __restrict__ w2g, const float* __restrict__ b2g,
    const float* __restrict__ beta, const float* __restrict__ x,
    float* __restrict__ out)
{
    __shared__ __align__(16) unsigned char smem[52224];
    float* sx0   = (float*)smem;
    float* sx1   = (float*)(smem + 10560);
    float* sraw  = (float*)smem;                        // overlay sx0
    ull*   sw2   = (ull*)(smem + 21120);
    float* smask = (float*)(smem + 21120);              // overlay sw2
    ull*   swx   = (ull*)(smem + 21120 + 11664);
    ull*   swy   = (ull*)(smem + 21120 + 11664 + 3888);

    const int tile = blockIdx.x;
    const int b    = blockIdx.y;
    const int r0   = tile * 3;
    const int tid  = threadIdx.x;
    const float sc = 80.0f / 323.0f;

    for (int i = tid; i < 9 * 432; i += 576) {
        const int co = i / 432, j = i - co * 432;
        const float w = (co < 8) ? w2o[co * 432 + j] : w2g[j];
        sw2[i] = pkf2(w, w);
    }

    const bool active = tid < 567;
    const int co  = active ? (tid / 63) : 0;
    const int s   = active ? (tid - co * 63) : 0;
    const int row = s / 21;
    const int tc  = (s - row * 21) * 4;
    const int nvalid = (tc == 80) ? 1 : 4;
    const int csel = (co == 8) ? 3 : 0;

    {
        const float4* src = (const float4*)g_hidden;
        for (int i = tid; i < C2F_F4; i += 576) {
            const int c  = i / 110;
            const int rm = i - c * 110;
            const int lr = rm / 22;
            const int f4 = rm - lr * 22;
            const int ch = (c < 3) ? c : (48 + c - 3);
            ((float4*)sx0)[(c * 5 + lr) * 22 + f4] =
                src[((b * 96 + ch) * XPP + (r0 + lr) * XPW) / 4 + f4];
        }
    }
    __syncthreads();

    ull a0 = 0ULL, a1 = 0ULL;

    for (int cc = 0; cc < 16; ++cc) {
        float* cursx = (cc & 1) ? sx1 : sx0;
        float* nxtsx = (cc & 1) ? sx0 : sx1;

        if (cc < 15) {
            const float4* src = (const float4*)g_hidden;
            for (int i = tid; i < C2F_F4; i += 576) {
                const int c  = i / 110;
                const int rm = i - c * 110;
                const int lr = rm / 22;
                const int f4 = rm - lr * 22;
                const int ch = (c < 3) ? ((cc + 1) * 3 + c) : (48 + (cc + 1) * 3 + (c - 3));
                ((float4*)nxtsx)[(c * 5 + lr) * 22 + f4] =
                    src[((b * 96 + ch) * XPP + (r0 + lr) * XPW) / 4 + f4];
            }
        }

        if (active) {
#pragma unroll
            for (int c = 0; c < 3; ++c) {
                ull PA[3], PAB[3], PB[3], PBC[3], PC[3];
#pragma unroll
                for (int rr = 0; rr < 3; ++rr) {
                    const float* rp = &cursx[((csel + c) * 5 + row + rr) * XPW + tc];
                    const ull A  = *(const ull*)rp;
                    const ull Bv = *(const ull*)(rp + 2);
                    const ull Cv = *(const ull*)(rp + 4);
                    PA[rr] = A; PB[rr] = Bv; PC[rr] = Cv;
                    PAB[rr] = hilo(A, Bv); PBC[rr] = hilo(Bv, Cv);
                }
                const int wb = co * 432 + (cc * 3 + c) * 9;
#pragma unroll
                for (int ky = 0; ky < 3; ++ky)
#pragma unroll
                    for (int kx = 0; kx < 3; ++kx) {
                        const ull w = sw2[wb + ky * 3 + kx];
                        ffma2(a0, kx == 0 ? PA[ky] : (kx == 1 ? PAB[ky] : PB[ky]), w);
                        ffma2(a1, kx == 0 ? PB[ky] : (kx == 1 ? PBC[ky] : PC[ky]), w);
                    }
            }
        }
        __syncthreads();
    }

    // ---- epilogue: activations -> sraw (+ v -> out) ----
    if (active) {
        const float bias = (co < 8) ? b2o[co] : b2g[0];
        float v[4];
        upkf2(a0, v[0], v[1]);
        upkf2(a1, v[2], v[3]);
#pragma unroll
        for (int p = 0; p < 4; ++p) {
            if (p >= nvalid) continue;
            const float raw = v[p] + bias;
            if (co < 8) {
                const float t = fast_tanh(raw);
                sraw[co * 252 + row * 84 + tc + p] = t;
                out[OUT_V_OFF + (b * 8 + co) * HW + (r0 + row) * WL + tc + p] = t;
            } else {
                sraw[8 * 252 + row * 84 + tc + p] = fast_sigmoid(raw);
            }
        }
    }
    __syncthreads();

    // ---- phase 2: masks + geometry + g_up ----
    if (tid < 243) {
        const int rowl = tid / 81;
        const int xx   = tid - rowl * 81;
        const int sb   = rowl * 84 + xx;

        const float p0 = sraw[0 * 252 + sb] - sraw[4 * 252 + sb];
        const float p1 = sraw[1 * 252 + sb] - sraw[5 * 252 + sb];
        const float p2 = sraw[2 * 252 + sb] - sraw[6 * 252 + sb];
        const float p3 = sraw[3 * 252 + sb] - sraw[7 * 252 + sb];
        const float g  = sraw[8 * 252 + sb];

        const float k00 = (p0 + p1 + p2) * 0.125f;
        const float k01 = (p1 + p2 + p3) * 0.125f;
        const float k02 = (-p0 + p2 + p3) * 0.125f;
        const float k10 = (p0 + p1 - p3) * 0.125f;

        float kb[9];
        kb[0] = k00;  kb[1] = k01;  kb[2] = k02;
        kb[3] = k10;  kb[4] = 2.5f; kb[5] = -k10;
        kb[6] = -k02; kb[7] = -k01; kb[8] = -k00;

        float mx = kb[0];
#pragma unroll
        for (int n = 1; n < 9; ++n) mx = fmaxf(mx, kb[n]);
        float e[9], se = 0.f;
#pragma unroll
        for (int n = 0; n < 9; ++n) { e[n] = __expf((kb[n] - mx) * 2.0f); se += e[n]; }
        const float inv_se = __fdividef(1.0f, se);

        const float mean = 2.5f / 9.0f;
        float sa = 0.f;
#pragma unroll
        for (int n = 0; n < 9; ++n) sa += fabsf(kb[n] - mean);
        const float hinv = __fdividef(1.0f, sa + 1e-8f);

        const float lam = 0.15f * (1.0f - g);
        const float tbg = tanhf(beta[0]) * g;

        float w[12];
#pragma unroll
        for (int n = 0; n < 9; ++n) w[n] = lam * e[n] * inv_se + tbg * (kb[n] - mean) * hinv;
        w[9]  = 1.0f - lam;
        w[10] = g;
        w[11] = 0.f;

        float* dm = &smask[tid * 12];
        ((float4*)dm)[0] = make_float4(w[0], w[1], w[2], w[3]);
        ((float4*)dm)[1] = make_float4(w[4], w[5], w[6], w[7]);
        ((float4*)dm)[2] = make_float4(w[8], w[9], w[10], w[11]);

        const int y = r0 + rowl;
        const float4 gq = make_float4(g, g, g, g);
        float* gd = &out[OUT_G_OFF + b * HWO + (y * 4) * WOUTX + xx * 4];
#pragma unroll
        for (int jy = 0; jy < 4; ++jy) *(float4*)(gd + jy * WOUTX) = gq;
    } else if (tid >= 288 && tid < 369) {
        const int q = tid - 288;
        float w3[4][3];
#pragma unroll
        for (int j = 0; j < 4; ++j) {
            const float f = (float)(q * 4 + j) * sc;
            int i0 = (int)f; if (i0 > 79) i0 = 79;
            const float w = f - (float)i0;
            const bool lo = (i0 != q);
            w3[j][0] = lo ? (1.f - w) : 0.f;
            w3[j][1] = lo ? w : (1.f - w);
            w3[j][2] = lo ? 0.f : w;
        }
#pragma unroll
        for (int p = 0; p < 2; ++p)
#pragma unroll
            for (int j = 0; j < 3; ++j)
                swx[q * 6 + p * 3 + j] = pkf2(w3[2 * p][j], w3[2 * p + 1][j]);
    } else if (tid >= 384 && tid < 396) {
        const int t2 = tid - 384;
        const int rowl = t2 / 4, jy = t2 - (t2 / 4) * 4;
        const int q = r0 + rowl;
        const float f = (float)(q * 4 + jy) * sc;
        int i0 = (int)f; if (i0 > 79) i0 = 79;
        const float w = f - (float)i0;
        const bool lo = (i0 != q);
        const float t0 = lo ? (1.f - w) : 0.f;
        const float t1 = lo ? w : (1.f - w);
        const float t2f = lo ? 0.f : w;
        swy[(rowl * 4 + jy) * 3 + 0] = pkf2(t0, t0);
        swy[(rowl * 4 + jy) * 3 + 1] = pkf2(t1, t1);
        swy[(rowl * 4 + jy) * 3 + 2] = pkf2(t2f, t2f);
    }
    __syncthreads();

    // ---- phase 3: upsample ----
    for (int t = tid; t < 5103; t += 576) {
        const int ch   = t / 243;
        const int pxl  = t - ch * 243;
        const int rowl = pxl / 81;
        const int xx   = pxl - rowl * 81;
        const int y    = r0 + rowl;

        const float* wsrc = &smask[pxl * 12];
        const float4 m0 = ((const float4*)wsrc)[0];
        const float4 m1 = ((const float4*)wsrc)[1];
        const float4 m2 = ((const float4*)wsrc)[2];
        const float wm[9] = {m0.x, m0.y, m0.z, m0.w, m1.x, m1.y, m1.z, m1.w, m2.x};
        const float oml = m2.y;
        const ull oml2 = pkf2(oml, oml);

        const int ym = (y == 0) ? 1 : y - 1,   ypl = (y == HL - 1) ? HL - 2 : y + 1;
        const int xm = (xx == 0) ? 1 : xx - 1, xpl = (xx == WL - 1) ? WL - 2 : xx + 1;
        const int ry[3] = {ym, y, ypl};
        const int rx[3] = {xm, xx, xpl};

        const float* xb = x + (b * CIN + ch) * HW;
        float tv[3][3];
#pragma unroll
        for (int i = 0; i < 3; ++i)
#pragma unroll
            for (int j = 0; j < 3; ++j)
                tv[i][j] = xb[ry[i] * WL + rx[j]];

        float yc = 0.f;
#pragma unroll
        for (int i = 0; i < 3; ++i)
#pragma unroll
            for (int j = 0; j < 3; ++j)
                yc += tv[i][j] * wm[i * 3 + j];
        const ull yc2 = pkf2(yc, yc);

        ull wxp[6];
#pragma unroll
        for (int i = 0; i < 6; ++i) wxp[i] = swx[xx * 6 + i];

        ull cvp[3][2];
#pragma unroll
        for (int i = 0; i < 3; ++i) { cvp[i][0] = 0ULL; cvp[i][1] = 0ULL; }
#pragma unroll
        for (int i = 0; i < 3; ++i)
#pragma unroll
            for (int j = 0; j < 3; ++j) {
                const ull td = pkf2(tv[i][j], tv[i][j]);
                ffma2(cvp[i][0], td, wxp[j]);
                ffma2(cvp[i][1], td, wxp[3 + j]);
            }

        float* dst = &out[(b * CIN + ch) * HWO + (y * 4) * WOUTX + xx * 4];
#pragma unroll
        for (int jy = 0; jy < 4; ++jy) {
            ull bil0 = 0ULL, bil1 = 0ULL;
#pragma unroll
            for (int i = 0; i < 3; ++i) {
                const ull wy = swy[(rowl * 4 + jy) * 3 + i];
                ffma2(bil0, cvp[i][0], wy);
                ffma2(bil1, cvp[i][1], wy);
            }
            ull rr0 = yc2, rr1 = yc2;
            ffma2(rr0, bil0, oml2);
            ffma2(rr1, bil1, oml2);
            float o0, o1, o2, o3;
            upkf2(rr0, o0, o1);
            upkf2(rr1, o2, o3);
            *(float4*)(dst + jy * WOUTX) = make_float4(o0, o1, o2, o3);
        }
    }
}

// ==========================================================================
extern "C" void kernel_launch(void* const* d_in, const int* in_sizes, int n_in,
                              void* d_out, int out_size)
{
    const float* x    = (const float*)d_in[0];
    const float* w1o  = (const float*)d_in[1];
    const float* b1o  = (const float*)d_in[2];
    const float* w2o  = (const float*)d_in[3];
    const float* b2o  = (const float*)d_in[4];
    const float* w1g  = (const float*)d_in[5];
    const float* b1g  = (const float*)d_in[6];
    const float* w2g  = (const float*)d_in[7];
    const float* b2g  = (const float*)d_in[8];
    const float* beta = (const float*)d_in[9];
    float* out = (float*)d_out;

    pad_kernel<<<dim3(27, CIN), dim3(81, 3)>>>(x);
    conv1_kernel<<<dim3(3, 24, Bn), 192>>>(w1o, b1o, w1g, b1g);
    conv2fused_kernel<<<dim3(27, Bn), 576>>>(w2o, b2o, w2g, b2g, beta, x, out);
    probe_kernel<<<1, 32>>>();   // shifts ncu's skip-5 capture onto conv1
}

// round 17
// speedup vs baseline: 1.1800x; 1.0265x over previous
#include <cuda_runtime.h>
#include <math.h>

typedef unsigned long long ull;

// ---------------- problem constants ----------------
#define Bn    4
#define CIN   21
#define HL    81
#define WL    81
#define HW    6561
#define HWO   104976
#define WOUTX 324
#define XPW   88
#define XPP   7304        // 83*88

#define OUT_V_OFF 8817984
#define OUT_G_OFF 9027936

// ---------------- scratch (zero-init BSS: halos stay zero forever) --------
__device__ float g_xpad[Bn * CIN * XPP];
__device__ float g_hidden[Bn * 96 * XPP];

// ---------------- packed fp32x2 helpers ----------------
__device__ __forceinline__ ull pkf2(float lo, float hi) {
    ull r; asm("mov.b64 %0, {%1,%2};" : "=l"(r) : "f"(lo), "f"(hi)); return r;
}
__device__ __forceinline__ void upkf2(ull v, float& lo, float& hi) {
    asm("mov.b64 {%0,%1}, %2;" : "=f"(lo), "=f"(hi) : "l"(v));
}
__device__ __forceinline__ void ffma2(ull& d, ull a, ull b) {
    asm("fma.rn.f32x2 %0, %1, %2, %0;" : "+l"(d) : "l"(a), "l"(b));
}
__device__ __forceinline__ ull hilo(ull a, ull b) {
    float al, ah, bl, bh; upkf2(a, al, ah); upkf2(b, bl, bh); return pkf2(ah, bl);
}

__device__ __forceinline__ float fast_tanh(float x) {
    const float e2 = __expf(2.0f * x);
    return 1.0f - __fdividef(2.0f, e2 + 1.0f);
}
__device__ __forceinline__ float fast_sigmoid(float x) {
    return __fdividef(1.0f, 1.0f + __expf(-x));
}

// ==========================================================================
// Kernel 0: interior-only copy x -> xpad, 4 batches per thread (MLP 4).
// grid (27, 21); block (81, 3).
// ==========================================================================
__global__ __launch_bounds__(243) void pad_kernel(const float* __restrict__ x)
{
    const int c   = blockIdx.y;
    const int row = blockIdx.x * 3 + threadIdx.y;
    const int col = threadIdx.x;
    const int srel = row * WL + col;
    const int drel = (row + 1) * XPW + col + 1;
#pragma unroll
    for (int b = 0; b < Bn; ++b)
        g_xpad[(b * CIN + c) * XPP + drel] = x[(b * CIN + c) * HW + srel];
}

// ==========================================================================
// Kernel 1: conv1 (21 -> 96), ReLU. Double-buffered; staging fully
// unrolled (MLP 10). grid (3, 24, Bn); block 192 (189 active).
// ==========================================================================
#define C1_F4 (3 * 29 * 22)
__global__ __launch_bounds__(192) void conv1_kernel(
    const float* __restrict__ w1o, const float* __restrict__ b1o,
    const float* __restrict__ w1g, const float* __restrict__ b1g)
{
    __shared__ __align__(16) float sx[2][3 * 29 * XPW];
    __shared__ ull sw2[4 * 189];

    const int tile = blockIdx.x;
    const int cg   = blockIdx.y;
    const int b    = blockIdx.z;
    const int r0   = tile * 27;
    const int tid  = threadIdx.x;

    for (int i = tid; i < 4 * 189; i += 192) {
        const int co = i / 189, j = i - co * 189;
        const int co_out = cg * 4 + co;
        const float w = (co_out < 48) ? w1o[co_out * 189 + j] : w1g[(co_out - 48) * 189 + j];
        sw2[i] = pkf2(w, w);
    }

    const bool active = tid < 189;
    const int trp = active ? (tid / 21) : 0;
    const int tc  = active ? ((tid - trp * 21) * 4) : 0;
    const int trp3 = trp * 3;
    const int nvalid = (tc == 80) ? 1 : 4;

    {
        const float4* src = (const float4*)g_xpad;
#pragma unroll
        for (int k = 0; k < 10; ++k) {
            const int i = tid + k * 192;
            if (i < C1_F4) {
                const int c  = i / 638;
                const int rm = i - c * 638;
                const int lr = rm / 22;
                const int f4 = rm - lr * 22;
                ((float4*)sx[0])[(c * 29 + lr) * 22 + f4] =
                    src[((b * CIN + c) * XPP + (r0 + lr) * XPW) / 4 + f4];
            }
        }
    }
    __syncthreads();

    ull acc[4][3][2];
#pragma unroll
    for (int co = 0; co < 4; ++co)
#pragma unroll
        for (int r = 0; r < 3; ++r) { acc[co][r][0] = 0ULL; acc[co][r][1] = 0ULL; }

    for (int cc = 0; cc < 7; ++cc) {
        const int cur = cc & 1;
        if (cc < 6) {
            const float4* src = (const float4*)g_xpad;
#pragma unroll
            for (int k = 0; k < 10; ++k) {
                const int i = tid + k * 192;
                if (i < C1_F4) {
                    const int c  = i / 638;
                    const int rm = i - c * 638;
                    const int lr = rm / 22;
                    const int f4 = rm - lr * 22;
                    ((float4*)sx[cur ^ 1])[(c * 29 + lr) * 22 + f4] =
                        src[((b * CIN + (cc + 1) * 3 + c) * XPP + (r0 + lr) * XPW) / 4 + f4];
                }
            }
        }

        if (active) {
#pragma unroll
            for (int c = 0; c < 3; ++c) {
                ull PA[5], PAB[5], PB[5], PBC[5], PC[5];
#pragma unroll
                for (int rr = 0; rr < 5; ++rr) {
                    const float* rp = &sx[cur][(c * 29 + trp3 + rr) * XPW + tc];
                    const ull A  = *(const ull*)rp;
                    const ull Bv = *(const ull*)(rp + 2);
                    const ull Cv = *(const ull*)(rp + 4);
                    PA[rr] = A; PB[rr] = Bv; PC[rr] = Cv;
                    PAB[rr] = hilo(A, Bv); PBC[rr] = hilo(Bv, Cv);
                }
                const int wb = (cc * 3 + c) * 9;
#pragma unroll
                for (int ky = 0; ky < 3; ++ky)
#pragma unroll
                    for (int kx = 0; kx < 3; ++kx)
#pragma unroll
                        for (int co = 0; co < 4; ++co) {
                            const ull w = sw2[co * 189 + wb + ky * 3 + kx];
#pragma unroll
                            for (int r = 0; r < 3; ++r) {
                                const int rw = r + ky;
                                ffma2(acc[co][r][0],
                                      kx == 0 ? PA[rw] : (kx == 1 ? PAB[rw] : PB[rw]), w);
                                ffma2(acc[co][r][1],
                                      kx == 0 ? PB[rw] : (kx == 1 ? PBC[rw] : PC[rw]), w);
                            }
                        }
            }
        }
        if (cc < 6) __syncthreads();
    }

    if (active) {
#pragma unroll
        for (int co = 0; co < 4; ++co) {
            const int co_out = cg * 4 + co;
            const float bias = (co_out < 48) ? b1o[co_out] : b1g[co_out - 48];
#pragma unroll
            for (int r = 0; r < 3; ++r) {
                const int orow = r0 + trp3 + r;
                float* dst = &g_hidden[(b * 96 + co_out) * XPP + (orow + 1) * XPW + tc + 1];
                float v[4];
                upkf2(acc[co][r][0], v[0], v[1]);
                upkf2(acc[co][r][1], v[2], v[3]);
#pragma unroll
                for (int p = 0; p < 4; ++p)
                    if (p < nvalid) dst[p] = fmaxf(v[p] + bias, 0.f);
            }
        }
    }
}

// ==========================================================================
// Kernel 2 (FUSED): conv2 heads + mask + upsample. Staging loops fully
// unrolled (front-batched LDG.128). grid (27, Bn); block 576.
// ==========================================================================
#define C2F_F4 660
__global__ __launch_bounds__(576) void conv2fused_kernel(
    const float* __restrict__ w2o, const float* __restrict__ b2o,
    const float* __restrict__ w2g, const float* __restrict__ b2g,
    const float* __restrict__ beta, const float* __restrict__ x,
    float* __restrict__ out)
{
    __shared__ __align__(16) unsigned char smem[52224];
    float* sx0   = (float*)smem;
    float* sx1   = (float*)(smem + 10560);
    float* sraw  = (float*)smem;                        // overlay sx0
    ull*   sw2   = (ull*)(smem + 21120);
    float* smask = (float*)(smem + 21120);              // overlay sw2
    ull*   swx   = (ull*)(smem + 21120 + 11664);
    ull*   swy   = (ull*)(smem + 21120 + 11664 + 3888);

    const int tile = blockIdx.x;
    const int b    = blockIdx.y;
    const int r0   = tile * 3;
    const int tid  = threadIdx.x;
    const float sc = 80.0f / 323.0f;

    for (int i = tid; i < 9 * 432; i += 576) {
        const int co = i / 432, j = i - co * 432;
        const float w = (co < 8) ? w2o[co * 432 + j] : w2g[j];
        sw2[i] = pkf2(w, w);
    }

    const bool active = tid < 567;
    const int co  = active ? (tid / 63) : 0;
    const int s   = active ? (tid - co * 63) : 0;
    const int row = s / 21;
    const int tc  = (s - row * 21) * 4;
    const int nvalid = (tc == 80) ? 1 : 4;
    const int csel = (co == 8) ? 3 : 0;

    {
        const float4* src = (const float4*)g_hidden;
#pragma unroll
        for (int k = 0; k < 2; ++k) {
            const int i = tid + k * 576;
            if (i < C2F_F4) {
                const int c  = i / 110;
                const int rm = i - c * 110;
                const int lr = rm / 22;
                const int f4 = rm - lr * 22;
                const int ch = (c < 3) ? c : (48 + c - 3);
                ((float4*)sx0)[(c * 5 + lr) * 22 + f4] =
                    src[((b * 96 + ch) * XPP + (r0 + lr) * XPW) / 4 + f4];
            }
        }
    }
    __syncthreads();

    ull a0 = 0ULL, a1 = 0ULL;

    for (int cc = 0; cc < 16; ++cc) {
        float* cursx = (cc & 1) ? sx1 : sx0;
        float* nxtsx = (cc & 1) ? sx0 : sx1;

        if (cc < 15) {
            const float4* src = (const float4*)g_hidden;
#pragma unroll
            for (int k = 0; k < 2; ++k) {
                const int i = tid + k * 576;
                if (i < C2F_F4) {
                    const int c  = i / 110;
                    const int rm = i - c * 110;
                    const int lr = rm / 22;
                    const int f4 = rm - lr * 22;
                    const int ch = (c < 3) ? ((cc + 1) * 3 + c) : (48 + (cc + 1) * 3 + (c - 3));
                    ((float4*)nxtsx)[(c * 5 + lr) * 22 + f4] =
                        src[((b * 96 + ch) * XPP + (r0 + lr) * XPW) / 4 + f4];
                }
            }
        }

        if (active) {
#pragma unroll
            for (int c = 0; c < 3; ++c) {
                ull PA[3], PAB[3], PB[3], PBC[3], PC[3];
#pragma unroll
                for (int rr = 0; rr < 3; ++rr) {
                    const float* rp = &cursx[((csel + c) * 5 + row + rr) * XPW + tc];
                    const ull A  = *(const ull*)rp;
                    const ull Bv = *(const ull*)(rp + 2);
                    const ull Cv = *(const ull*)(rp + 4);
                    PA[rr] = A; PB[rr] = Bv; PC[rr] = Cv;
                    PAB[rr] = hilo(A, Bv); PBC[rr] = hilo(Bv, Cv);
                }
                const int wb = co * 432 + (cc * 3 + c) * 9;
#pragma unroll
                for (int ky = 0; ky < 3; ++ky)
#pragma unroll
                    for (int kx = 0; kx < 3; ++kx) {
                        const ull w = sw2[wb + ky * 3 + kx];
                        ffma2(a0, kx == 0 ? PA[ky] : (kx == 1 ? PAB[ky] : PB[ky]), w);
                        ffma2(a1, kx == 0 ? PB[ky] : (kx == 1 ? PBC[ky] : PC[ky]), w);
                    }
            }
        }
        __syncthreads();
    }

    // ---- epilogue: activations -> sraw (+ v -> out) ----
    if (active) {
        const float bias = (co < 8) ? b2o[co] : b2g[0];
        float v[4];
        upkf2(a0, v[0], v[1]);
        upkf2(a1, v[2], v[3]);
#pragma unroll
        for (int p = 0; p < 4; ++p) {
            if (p >= nvalid) continue;
            const float raw = v[p] + bias;
            if (co < 8) {
                const float t = fast_tanh(raw);
                sraw[co * 252 + row * 84 + tc + p] = t;
                out[OUT_V_OFF + (b * 8 + co) * HW + (r0 + row) * WL + tc + p] = t;
            } else {
                sraw[8 * 252 + row * 84 + tc + p] = fast_sigmoid(raw);
            }
        }
    }
    __syncthreads();

    // ---- phase 2: masks + geometry + g_up ----
    if (tid < 243) {
        const int rowl = tid / 81;
        const int xx   = tid - rowl * 81;
        const int sb   = rowl * 84 + xx;

        const float p0 = sraw[0 * 252 + sb] - sraw[4 * 252 + sb];
        const float p1 = sraw[1 * 252 + sb] - sraw[5 * 252 + sb];
        const float p2 = sraw[2 * 252 + sb] - sraw[6 * 252 + sb];
        const float p3 = sraw[3 * 252 + sb] - sraw[7 * 252 + sb];
        const float g  = sraw[8 * 252 + sb];

        const float k00 = (p0 + p1 + p2) * 0.125f;
        const float k01 = (p1 + p2 + p3) * 0.125f;
        const float k02 = (-p0 + p2 + p3) * 0.125f;
        const float k10 = (p0 + p1 - p3) * 0.125f;

        float kb[9];
        kb[0] = k00;  kb[1] = k01;  kb[2] = k02;
        kb[3] = k10;  kb[4] = 2.5f; kb[5] = -k10;
        kb[6] = -k02; kb[7] = -k01; kb[8] = -k00;

        float mx = kb[0];
#pragma unroll
        for (int n = 1; n < 9; ++n) mx = fmaxf(mx, kb[n]);
        float e[9], se = 0.f;
#pragma unroll
        for (int n = 0; n < 9; ++n) { e[n] = __expf((kb[n] - mx) * 2.0f); se += e[n]; }
        const float inv_se = __fdividef(1.0f, se);

        const float mean = 2.5f / 9.0f;
        float sa = 0.f;
#pragma unroll
        for (int n = 0; n < 9; ++n) sa += fabsf(kb[n] - mean);
        const float hinv = __fdividef(1.0f, sa + 1e-8f);

        const float lam = 0.15f * (1.0f - g);
        const float tbg = tanhf(beta[0]) * g;

        float w[12];
#pragma unroll
        for (int n = 0; n < 9; ++n) w[n] = lam * e[n] * inv_se + tbg * (kb[n] - mean) * hinv;
        w[9]  = 1.0f - lam;
        w[10] = g;
        w[11] = 0.f;

        float* dm = &smask[tid * 12];
        ((float4*)dm)[0] = make_float4(w[0], w[1], w[2], w[3]);
        ((float4*)dm)[1] = make_float4(w[4], w[5], w[6], w[7]);
        ((float4*)dm)[2] = make_float4(w[8], w[9], w[10], w[11]);

        const int y = r0 + rowl;
        const float4 gq = make_float4(g, g, g, g);
        float* gd = &out[OUT_G_OFF + b * HWO + (y * 4) * WOUTX + xx * 4];
#pragma unroll
        for (int jy = 0; jy < 4; ++jy) *(float4*)(gd + jy * WOUTX) = gq;
    } else if (tid >= 288 && tid < 369) {
        const int q = tid - 288;
        float w3[4][3];
#pragma unroll
        for (int j = 0; j < 4; ++j) {
            const float f = (float)(q * 4 + j) * sc;
            int i0 = (int)f; if (i0 > 79) i0 = 79;
            const float w = f - (float)i0;
            const bool lo = (i0 != q);
            w3[j][0] = lo ? (1.f - w) : 0.f;
            w3[j][1] = lo ? w : (1.f - w);
            w3[j][2] = lo ? 0.f : w;
        }
#pragma unroll
        for (int p = 0; p < 2; ++p)
#pragma unroll
            for (int j = 0; j < 3; ++j)
                swx[q * 6 + p * 3 + j] = pkf2(w3[2 * p][j], w3[2 * p + 1][j]);
    } else if (tid >= 384 && tid < 396) {
        const int t2 = tid - 384;
        const int rowl = t2 / 4, jy = t2 - (t2 / 4) * 4;
        const int q = r0 + rowl;
        const float f = (float)(q * 4 + jy) * sc;
        int i0 = (int)f; if (i0 > 79) i0 = 79;
        const float w = f - (float)i0;
        const bool lo = (i0 != q);
        const float t0 = lo ? (1.f - w) : 0.f;
        const float t1 = lo ? w : (1.f - w);
        const float t2f = lo ? 0.f : w;
        swy[(rowl * 4 + jy) * 3 + 0] = pkf2(t0, t0);
        swy[(rowl * 4 + jy) * 3 + 1] = pkf2(t1, t1);
        swy[(rowl * 4 + jy) * 3 + 2] = pkf2(t2f, t2f);
    }
    __syncthreads();

    // ---- phase 3: upsample ----
    for (int t = tid; t < 5103; t += 576) {
        const int ch   = t / 243;
        const int pxl  = t - ch * 243;
        const int rowl = pxl / 81;
        const int xx   = pxl - rowl * 81;
        const int y    = r0 + rowl;

        const float* wsrc = &smask[pxl * 12];
        const float4 m0 = ((const float4*)wsrc)[0];
        const float4 m1 = ((const float4*)wsrc)[1];
        const float4 m2 = ((const float4*)wsrc)[2];
        const float wm[9] = {m0.x, m0.y, m0.z, m0.w, m1.x, m1.y, m1.z, m1.w, m2.x};
        const float oml = m2.y;
        const ull oml2 = pkf2(oml, oml);

        const int ym = (y == 0) ? 1 : y - 1,   ypl = (y == HL - 1) ? HL - 2 : y + 1;
        const int xm = (xx == 0) ? 1 : xx - 1, xpl = (xx == WL - 1) ? WL - 2 : xx + 1;
        const int ry[3] = {ym, y, ypl};
        const int rx[3] = {xm, xx, xpl};

        const float* xb = x + (b * CIN + ch) * HW;
        float tv[3][3];
#pragma unroll
        for (int i = 0; i < 3; ++i)
#pragma unroll
            for (int j = 0; j < 3; ++j)
                tv[i][j] = xb[ry[i] * WL + rx[j]];

        float yc = 0.f;
#pragma unroll
        for (int i = 0; i < 3; ++i)
#pragma unroll
            for (int j = 0; j < 3; ++j)
                yc += tv[i][j] * wm[i * 3 + j];
        const ull yc2 = pkf2(yc, yc);

        ull wxp[6];
#pragma unroll
        for (int i = 0; i < 6; ++i) wxp[i] = swx[xx * 6 + i];

        ull cvp[3][2];
#pragma unroll
        for (int i = 0; i < 3; ++i) { cvp[i][0] = 0ULL; cvp[i][1] = 0ULL; }
#pragma unroll
        for (int i = 0; i < 3; ++i)
#pragma unroll
            for (int j = 0; j < 3; ++j) {
                const ull td = pkf2(tv[i][j], tv[i][j]);
                ffma2(cvp[i][0], td, wxp[j]);
                ffma2(cvp[i][1], td, wxp[3 + j]);
            }

        float* dst = &out[(b * CIN + ch) * HWO + (y * 4) * WOUTX + xx * 4];
#pragma unroll
        for (int jy = 0; jy < 4; ++jy) {
            ull bil0 = 0ULL, bil1 = 0ULL;
#pragma unroll
            for (int i = 0; i < 3; ++i) {
                const ull wy = swy[(rowl * 4 + jy) * 3 + i];
                ffma2(bil0, cvp[i][0], wy);
                ffma2(bil1, cvp[i][1], wy);
            }
            ull rr0 = yc2, rr1 = yc2;
            ffma2(rr0, bil0, oml2);
            ffma2(rr1, bil1, oml2);
            float o0, o1, o2, o3;
            upkf2(rr0, o0, o1);
            upkf2(rr1, o2, o3);
            *(float4*)(dst + jy * WOUTX) = make_float4(o0, o1, o2, o3);
        }
    }
}

// ==========================================================================
extern "C" void kernel_launch(void* const* d_in, const int* in_sizes, int n_in,
                              void* d_out, int out_size)
{
    const float* x    = (const float*)d_in[0];
    const float* w1o  = (const float*)d_in[1];
    const float* b1o  = (const float*)d_in[2];
    const float* w2o  = (const float*)d_in[3];
    const float* b2o  = (const float*)d_in[4];
    const float* w1g  = (const float*)d_in[5];
    const float* b1g  = (const float*)d_in[6];
    const float* w2g  = (const float*)d_in[7];
    const float* b2g  = (const float*)d_in[8];
    const float* beta = (const float*)d_in[9];
    float* out = (float*)d_out;

    pad_kernel<<<dim3(27, CIN), dim3(81, 3)>>>(x);
    conv1_kernel<<<dim3(3, 24, Bn), 192>>>(w1o, b1o, w1g, b1g);
    conv2fused_kernel<<<dim3(27, Bn), 576>>>(w2o, b2o, w2g, b2g, beta, x, out);
}